// round 1
// baseline (speedup 1.0000x reference)
#include <cuda_runtime.h>
#include <math.h>

#define NLOC 8192
#define SEQ 32
#define CDIM 128
#define NHEAD 8
#define HD 16
#define MROWS (NLOC*SEQ)   // 262144
#define FFND 512

// -------- scratch (static device globals; no runtime allocation) --------
__device__ float g_q[(size_t)MROWS * CDIM];   // 128 MB
__device__ float g_k[(size_t)MROWS * CDIM];   // 128 MB
__device__ float g_v[(size_t)MROWS * CDIM];   // 128 MB
__device__ float g_x1[(size_t)MROWS * CDIM];  // 128 MB
__device__ float g_h[(size_t)MROWS * FFND];   // 512 MB

// ============================================================
// Kernel 1: fused QKV projection (3 GEMMs, rows r = n*32 + s)
//   A[r][k] = x[s][n][k] ;  OUT[r][c] = sum_k A*W[k][c] + bias[c]
// ============================================================
__global__ __launch_bounds__(256, 2)
void k_qkv(const float* __restrict__ x,
           const float* __restrict__ wq, const float* __restrict__ bq,
           const float* __restrict__ wk, const float* __restrict__ bk,
           const float* __restrict__ wv, const float* __restrict__ bv)
{
    __shared__ float As[8][132];   // As[k][m] (transposed A tile)
    __shared__ float Bs[8][128];   // Bs[k][n]

    const int tid = threadIdx.x;
    const int tx = tid & 15;       // output col group
    const int ty = tid >> 4;       // output row group
    const int mt = blockIdx.x;
    const int which = blockIdx.y;

    const float* W;
    const float* BIAS;
    float* OUT;
    if (which == 0)      { W = wq; BIAS = bq; OUT = g_q; }
    else if (which == 1) { W = wk; BIAS = bk; OUT = g_k; }
    else                 { W = wv; BIAS = bv; OUT = g_v; }

    const int m0 = mt * 128;
    const int la_m = tid >> 1;
    const int la_k = (tid & 1) * 4;
    const int ar = m0 + la_m;
    const float* a_ptr = x + (size_t)(ar & 31) * (NLOC * CDIM)
                           + (size_t)(ar >> 5) * CDIM + la_k;
    const int lb_k = tid >> 5;
    const int lb_n = (tid & 31) * 4;
    const float* b_ptr = W + lb_k * CDIM + lb_n;

    float acc[8][8];
#pragma unroll
    for (int i = 0; i < 8; i++)
#pragma unroll
        for (int j = 0; j < 8; j++) acc[i][j] = 0.0f;

    for (int k0 = 0; k0 < CDIM; k0 += 8) {
        float4 av  = *(const float4*)(a_ptr + k0);
        float4 bv4 = *(const float4*)(b_ptr + (size_t)k0 * CDIM);
        __syncthreads();
        As[la_k + 0][la_m] = av.x;
        As[la_k + 1][la_m] = av.y;
        As[la_k + 2][la_m] = av.z;
        As[la_k + 3][la_m] = av.w;
        *(float4*)&Bs[lb_k][lb_n] = bv4;
        __syncthreads();
#pragma unroll
        for (int kk = 0; kk < 8; kk++) {
            float a[8], b[8];
            *(float4*)&a[0] = *(const float4*)&As[kk][ty * 8];
            *(float4*)&a[4] = *(const float4*)&As[kk][ty * 8 + 4];
            *(float4*)&b[0] = *(const float4*)&Bs[kk][tx * 8];
            *(float4*)&b[4] = *(const float4*)&Bs[kk][tx * 8 + 4];
#pragma unroll
            for (int i = 0; i < 8; i++)
#pragma unroll
                for (int j = 0; j < 8; j++)
                    acc[i][j] += a[i] * b[j];
        }
    }

    float bias[8];
    *(float4*)&bias[0] = *(const float4*)&BIAS[tx * 8];
    *(float4*)&bias[4] = *(const float4*)&BIAS[tx * 8 + 4];
#pragma unroll
    for (int i = 0; i < 8; i++) {
        const int r = m0 + ty * 8 + i;
        float4 o0, o1;
        o0.x = acc[i][0] + bias[0]; o0.y = acc[i][1] + bias[1];
        o0.z = acc[i][2] + bias[2]; o0.w = acc[i][3] + bias[3];
        o1.x = acc[i][4] + bias[4]; o1.y = acc[i][5] + bias[5];
        o1.z = acc[i][6] + bias[6]; o1.w = acc[i][7] + bias[7];
        *(float4*)&OUT[(size_t)r * CDIM + tx * 8]     = o0;
        *(float4*)&OUT[(size_t)r * CDIM + tx * 8 + 4] = o1;
    }
}

// ============================================================
// Kernel 2: attention per location n + residual + LayerNorm1
// ============================================================
#define PAD 132
__global__ __launch_bounds__(256)
void k_attn(const float* __restrict__ x,
            const float* __restrict__ ln1g, const float* __restrict__ ln1b)
{
    __shared__ float t0[SEQ][PAD];     // q (rotary), later v
    __shared__ float t1[SEQ][PAD];     // k (rotary), later attn-out O
    __shared__ float sinT[SEQ][8];
    __shared__ float cosT[SEQ][8];

    const int n = blockIdx.x;
    const int tid = threadIdx.x;

    // sin/cos table: angle[j] = 10000^(-j/7), j = d/2
    for (int idx = tid; idx < SEQ * 8; idx += 256) {
        const int s = idx >> 3, j = idx & 7;
        const float ang = powf(10000.0f, -(float)j / 7.0f);
        float sv, cv;
        sincosf((float)s * ang, &sv, &cv);
        sinT[s][j] = sv;
        cosT[s][j] = cv;
    }
    __syncthreads();

    const size_t base = (size_t)n * SEQ * CDIM;

    // Load q-hat, k-hat and apply rotary:
    //   out[d] = t[d]*cos + rot[d]*sin,  rot[d] = (d<8) ? -t[2d+1] : t[2d-16]
    for (int idx = tid; idx < SEQ * CDIM; idx += 256) {
        const int s = idx >> 7, c = idx & 127;
        const int h = c >> 4, hd = c & 15;
        const int pc = (hd < 8) ? (h * 16 + 2 * hd + 1) : (h * 16 + 2 * hd - 16);
        const float sgn = (hd < 8) ? -1.0f : 1.0f;
        const float sv = sinT[s][hd >> 1];
        const float cv = cosT[s][hd >> 1];
        {
            const float t = g_q[base + (size_t)s * CDIM + c];
            const float p = g_q[base + (size_t)s * CDIM + pc];
            t0[s][c] = t * cv + sgn * p * sv;
        }
        {
            const float t = g_k[base + (size_t)s * CDIM + c];
            const float p = g_k[base + (size_t)s * CDIM + pc];
            t1[s][c] = t * cv + sgn * p * sv;
        }
    }
    __syncthreads();

    const int warp = tid >> 5;   // = head h
    const int lane = tid & 31;   // = query position i
    float p[SEQ];
    float inv = 0.0f;
    {
        const int h = warp;
        float qr[HD];
#pragma unroll
        for (int d4 = 0; d4 < 4; d4++)
            *(float4*)&qr[d4 * 4] = *(const float4*)&t0[lane][h * 16 + d4 * 4];
        const float decay = log1pf(-exp2f(-(1.0f + 3.0f * (float)h / 8.0f)));
        float mx = -1e30f;
#pragma unroll
        for (int j = 0; j < SEQ; j++) {
            float kr[HD];
#pragma unroll
            for (int d4 = 0; d4 < 4; d4++)
                *(float4*)&kr[d4 * 4] = *(const float4*)&t1[j][h * 16 + d4 * 4];
            float dot = 0.0f;
#pragma unroll
            for (int d = 0; d < HD; d++) dot += qr[d] * kr[d];
            dot += fabsf((float)(lane - j)) * decay;
            p[j] = dot;
            mx = fmaxf(mx, dot);
        }
        float sum = 0.0f;
#pragma unroll
        for (int j = 0; j < SEQ; j++) { p[j] = expf(p[j] - mx); sum += p[j]; }
        inv = 1.0f / sum;
    }
    __syncthreads();   // all warps done reading q/k -> reuse t0 for v

    for (int idx = tid; idx < SEQ * CDIM; idx += 256) {
        const int s = idx >> 7, c = idx & 127;
        t0[s][c] = g_v[base + (size_t)s * CDIM + c];
    }
    __syncthreads();

    {
        float o[HD];
#pragma unroll
        for (int d = 0; d < HD; d++) o[d] = 0.0f;
#pragma unroll
        for (int j = 0; j < SEQ; j++) {
            float vr[HD];
#pragma unroll
            for (int d4 = 0; d4 < 4; d4++)
                *(float4*)&vr[d4 * 4] = *(const float4*)&t0[j][warp * 16 + d4 * 4];
#pragma unroll
            for (int d = 0; d < HD; d++) o[d] += p[j] * vr[d];
        }
        // write O into t1 (k is dead)
#pragma unroll
        for (int d4 = 0; d4 < 4; d4++) {
            float4 ov;
            ov.x = o[d4 * 4 + 0] * inv; ov.y = o[d4 * 4 + 1] * inv;
            ov.z = o[d4 * 4 + 2] * inv; ov.w = o[d4 * 4 + 3] * inv;
            *(float4*)&t1[lane][warp * 16 + d4 * 4] = ov;
        }
    }
    __syncthreads();

    // residual + LN1 -> g_x1 ; 8 warps x 4 rows
#pragma unroll
    for (int rr = 0; rr < 4; rr++) {
        const int s = warp * 4 + rr;
        const int c = lane * 4;
        float4 ov = *(const float4*)&t1[s][c];
        float4 xv = *(const float4*)&x[(size_t)s * NLOC * CDIM + (size_t)n * CDIM + c];
        float v0 = ov.x + xv.x, v1 = ov.y + xv.y, v2 = ov.z + xv.z, v3 = ov.w + xv.w;
        float sum = v0 + v1 + v2 + v3;
        float sq  = v0 * v0 + v1 * v1 + v2 * v2 + v3 * v3;
#pragma unroll
        for (int off = 16; off > 0; off >>= 1) {
            sum += __shfl_xor_sync(0xffffffffu, sum, off);
            sq  += __shfl_xor_sync(0xffffffffu, sq,  off);
        }
        const float mu  = sum * (1.0f / 128.0f);
        const float var = sq * (1.0f / 128.0f) - mu * mu;
        const float wn  = rsqrtf(var + 1e-5f);
        float4 g4 = *(const float4*)&ln1g[c];
        float4 b4 = *(const float4*)&ln1b[c];
        float4 o;
        o.x = (v0 - mu) * wn * g4.x + b4.x;
        o.y = (v1 - mu) * wn * g4.y + b4.y;
        o.z = (v2 - mu) * wn * g4.z + b4.z;
        o.w = (v3 - mu) * wn * g4.w + b4.w;
        *(float4*)&g_x1[base + (size_t)s * CDIM + c] = o;
    }
}

// ============================================================
// Kernel 3: FFN layer 1 : H = relu(X1 @ W1 + b1), N=512
// ============================================================
__global__ __launch_bounds__(256, 2)
void k_ffn1(const float* __restrict__ w1, const float* __restrict__ b1)
{
    __shared__ float As[8][132];
    __shared__ float Bs[8][128];

    const int tid = threadIdx.x;
    const int tx = tid & 15;
    const int ty = tid >> 4;
    const int m0 = blockIdx.x * 128;
    const int bn0 = blockIdx.y * 128;

    const int la_m = tid >> 1;
    const int la_k = (tid & 1) * 4;
    const float* a_ptr = g_x1 + (size_t)(m0 + la_m) * CDIM + la_k;
    const int lb_k = tid >> 5;
    const int lb_n = (tid & 31) * 4;
    const float* b_ptr = w1 + (size_t)lb_k * FFND + bn0 + lb_n;

    float acc[8][8];
#pragma unroll
    for (int i = 0; i < 8; i++)
#pragma unroll
        for (int j = 0; j < 8; j++) acc[i][j] = 0.0f;

    for (int k0 = 0; k0 < CDIM; k0 += 8) {
        float4 av  = *(const float4*)(a_ptr + k0);
        float4 bv4 = *(const float4*)(b_ptr + (size_t)k0 * FFND);
        __syncthreads();
        As[la_k + 0][la_m] = av.x;
        As[la_k + 1][la_m] = av.y;
        As[la_k + 2][la_m] = av.z;
        As[la_k + 3][la_m] = av.w;
        *(float4*)&Bs[lb_k][lb_n] = bv4;
        __syncthreads();
#pragma unroll
        for (int kk = 0; kk < 8; kk++) {
            float a[8], b[8];
            *(float4*)&a[0] = *(const float4*)&As[kk][ty * 8];
            *(float4*)&a[4] = *(const float4*)&As[kk][ty * 8 + 4];
            *(float4*)&b[0] = *(const float4*)&Bs[kk][tx * 8];
            *(float4*)&b[4] = *(const float4*)&Bs[kk][tx * 8 + 4];
#pragma unroll
            for (int i = 0; i < 8; i++)
#pragma unroll
                for (int j = 0; j < 8; j++)
                    acc[i][j] += a[i] * b[j];
        }
    }

    float bias[8];
    *(float4*)&bias[0] = *(const float4*)&b1[bn0 + tx * 8];
    *(float4*)&bias[4] = *(const float4*)&b1[bn0 + tx * 8 + 4];
#pragma unroll
    for (int i = 0; i < 8; i++) {
        const int r = m0 + ty * 8 + i;
        float4 o0, o1;
        o0.x = fmaxf(acc[i][0] + bias[0], 0.0f);
        o0.y = fmaxf(acc[i][1] + bias[1], 0.0f);
        o0.z = fmaxf(acc[i][2] + bias[2], 0.0f);
        o0.w = fmaxf(acc[i][3] + bias[3], 0.0f);
        o1.x = fmaxf(acc[i][4] + bias[4], 0.0f);
        o1.y = fmaxf(acc[i][5] + bias[5], 0.0f);
        o1.z = fmaxf(acc[i][6] + bias[6], 0.0f);
        o1.w = fmaxf(acc[i][7] + bias[7], 0.0f);
        *(float4*)&g_h[(size_t)r * FFND + bn0 + tx * 8]     = o0;
        *(float4*)&g_h[(size_t)r * FFND + bn0 + tx * 8 + 4] = o1;
    }
}

// ============================================================
// Kernel 4: FFN layer 2 + residual + LN2 + transposed output
//   Y = H @ W2 + b2 + X1 ; out[s][n][c] = LN2(Y[(n,s)])
// ============================================================
__global__ __launch_bounds__(256, 2)
void k_ffn2(const float* __restrict__ w2, const float* __restrict__ b2,
            const float* __restrict__ ln2g, const float* __restrict__ ln2b,
            float* __restrict__ out)
{
    __shared__ float As[8][132];
    __shared__ float Bs[8][128];

    const int tid = threadIdx.x;
    const int tx = tid & 15;
    const int ty = tid >> 4;
    const int m0 = blockIdx.x * 128;

    const int la_m = tid >> 1;
    const int la_k = (tid & 1) * 4;
    const float* a_ptr = g_h + (size_t)(m0 + la_m) * FFND + la_k;
    const int lb_k = tid >> 5;
    const int lb_n = (tid & 31) * 4;
    const float* b_ptr = w2 + (size_t)lb_k * CDIM + lb_n;

    float acc[8][8];
#pragma unroll
    for (int i = 0; i < 8; i++)
#pragma unroll
        for (int j = 0; j < 8; j++) acc[i][j] = 0.0f;

    for (int k0 = 0; k0 < FFND; k0 += 8) {
        float4 av  = *(const float4*)(a_ptr + k0);
        float4 bv4 = *(const float4*)(b_ptr + (size_t)k0 * CDIM);
        __syncthreads();
        As[la_k + 0][la_m] = av.x;
        As[la_k + 1][la_m] = av.y;
        As[la_k + 2][la_m] = av.z;
        As[la_k + 3][la_m] = av.w;
        *(float4*)&Bs[lb_k][lb_n] = bv4;
        __syncthreads();
#pragma unroll
        for (int kk = 0; kk < 8; kk++) {
            float a[8], b[8];
            *(float4*)&a[0] = *(const float4*)&As[kk][ty * 8];
            *(float4*)&a[4] = *(const float4*)&As[kk][ty * 8 + 4];
            *(float4*)&b[0] = *(const float4*)&Bs[kk][tx * 8];
            *(float4*)&b[4] = *(const float4*)&Bs[kk][tx * 8 + 4];
#pragma unroll
            for (int i = 0; i < 8; i++)
#pragma unroll
                for (int j = 0; j < 8; j++)
                    acc[i][j] += a[i] * b[j];
        }
    }

    float bias[8], g[8], bb[8];
    *(float4*)&bias[0] = *(const float4*)&b2[tx * 8];
    *(float4*)&bias[4] = *(const float4*)&b2[tx * 8 + 4];
    *(float4*)&g[0]    = *(const float4*)&ln2g[tx * 8];
    *(float4*)&g[4]    = *(const float4*)&ln2g[tx * 8 + 4];
    *(float4*)&bb[0]   = *(const float4*)&ln2b[tx * 8];
    *(float4*)&bb[4]   = *(const float4*)&ln2b[tx * 8 + 4];

#pragma unroll
    for (int i = 0; i < 8; i++) {
        const int r = m0 + ty * 8 + i;
        float v[8];
        float4 x1a = *(const float4*)&g_x1[(size_t)r * CDIM + tx * 8];
        float4 x1b = *(const float4*)&g_x1[(size_t)r * CDIM + tx * 8 + 4];
        v[0] = acc[i][0] + bias[0] + x1a.x;
        v[1] = acc[i][1] + bias[1] + x1a.y;
        v[2] = acc[i][2] + bias[2] + x1a.z;
        v[3] = acc[i][3] + bias[3] + x1a.w;
        v[4] = acc[i][4] + bias[4] + x1b.x;
        v[5] = acc[i][5] + bias[5] + x1b.y;
        v[6] = acc[i][6] + bias[6] + x1b.z;
        v[7] = acc[i][7] + bias[7] + x1b.w;
        float sum = 0.0f, sq = 0.0f;
#pragma unroll
        for (int j = 0; j < 8; j++) { sum += v[j]; sq += v[j] * v[j]; }
        // reduce across the 16 lanes (tx) sharing this row set
#pragma unroll
        for (int off = 8; off > 0; off >>= 1) {
            sum += __shfl_xor_sync(0xffffffffu, sum, off);
            sq  += __shfl_xor_sync(0xffffffffu, sq,  off);
        }
        const float mu  = sum * (1.0f / 128.0f);
        const float var = sq * (1.0f / 128.0f) - mu * mu;
        const float wn  = rsqrtf(var + 1e-5f);
        float4 o0, o1;
        o0.x = (v[0] - mu) * wn * g[0] + bb[0];
        o0.y = (v[1] - mu) * wn * g[1] + bb[1];
        o0.z = (v[2] - mu) * wn * g[2] + bb[2];
        o0.w = (v[3] - mu) * wn * g[3] + bb[3];
        o1.x = (v[4] - mu) * wn * g[4] + bb[4];
        o1.y = (v[5] - mu) * wn * g[5] + bb[5];
        o1.z = (v[6] - mu) * wn * g[6] + bb[6];
        o1.w = (v[7] - mu) * wn * g[7] + bb[7];
        const int nn = r >> 5;
        const int ss = r & 31;
        float* dst = out + (size_t)ss * NLOC * CDIM + (size_t)nn * CDIM + tx * 8;
        *(float4*)dst       = o0;
        *(float4*)(dst + 4) = o1;
    }
}

// ============================================================
extern "C" void kernel_launch(void* const* d_in, const int* in_sizes, int n_in,
                              void* d_out, int out_size)
{
    (void)in_sizes; (void)n_in; (void)out_size;
    const float* x    = (const float*)d_in[0];
    const float* wq   = (const float*)d_in[1];
    const float* bq   = (const float*)d_in[2];
    const float* wk   = (const float*)d_in[3];
    const float* bk   = (const float*)d_in[4];
    const float* wv   = (const float*)d_in[5];
    const float* bv   = (const float*)d_in[6];
    const float* ln1g = (const float*)d_in[7];
    const float* ln1b = (const float*)d_in[8];
    const float* w1   = (const float*)d_in[9];
    const float* b1   = (const float*)d_in[10];
    const float* w2   = (const float*)d_in[11];
    const float* b2   = (const float*)d_in[12];
    const float* ln2g = (const float*)d_in[13];
    const float* ln2b = (const float*)d_in[14];
    float* out = (float*)d_out;

    dim3 g1(MROWS / 128, 3);
    k_qkv<<<g1, 256>>>(x, wq, bq, wk, bk, wv, bv);

    k_attn<<<NLOC, 256>>>(x, ln1g, ln1b);

    dim3 g3(MROWS / 128, 4);
    k_ffn1<<<g3, 256>>>(w1, b1);

    k_ffn2<<<MROWS / 128, 256>>>(w2, b2, ln2g, ln2b, out);
}

// round 3
// speedup vs baseline: 1.9154x; 1.9154x over previous
#include <cuda_runtime.h>
#include <math.h>

#define NLOC 8192
#define SEQ 32
#define CDIM 128
#define NHEAD 8
#define HD 16
#define MROWS (NLOC*SEQ)   // 262144
#define FFND 512

// -------- scratch (static device globals; no runtime allocation) --------
__device__ float g_q[(size_t)MROWS * CDIM];
__device__ float g_k[(size_t)MROWS * CDIM];
__device__ float g_v[(size_t)MROWS * CDIM];
__device__ float g_x1[(size_t)MROWS * CDIM];
__device__ float g_h[(size_t)MROWS * FFND];

// ======================= tf32 MMA GEMM machinery =======================
// CTA tile 128x128, 8 warps (wm in 0..1 -> 64 rows, wn in 0..3 -> 32 cols),
// warp tile 64x32 via 4x4 m16n8k8 tf32 mma. K chunk = 32, double buffered.

#define AP 36                 // A smem pitch (floats): conflict-free fragment LDS
#define BP 136                // B smem pitch (floats): conflict-free fragment LDS
#define ASZ (128*AP)          // 4608 floats
#define BSZ (32*BP)           // 4352 floats
#define BUFSZ (ASZ+BSZ)       // 8960 floats
#define SMEM_FLOATS (2*BUFSZ) // 17920 floats = 71680 bytes
#define SMEM_BYTES (SMEM_FLOATS*4)

__device__ __forceinline__ float tf32r(float x) {
    unsigned u;
    asm("cvt.rna.tf32.f32 %0, %1;" : "=r"(u) : "f"(x));
    return __uint_as_float(u);
}
__device__ __forceinline__ void cvt4(float4& v) {
    v.x = tf32r(v.x); v.y = tf32r(v.y); v.z = tf32r(v.z); v.w = tf32r(v.w);
}

__device__ __forceinline__ void mma8(float* c, const float* a, const float* b) {
    asm volatile(
        "mma.sync.aligned.m16n8k8.row.col.f32.tf32.tf32.f32 "
        "{%0,%1,%2,%3}, {%4,%5,%6,%7}, {%8,%9}, {%0,%1,%2,%3};"
        : "+f"(c[0]), "+f"(c[1]), "+f"(c[2]), "+f"(c[3])
        : "r"(__float_as_uint(a[0])), "r"(__float_as_uint(a[1])),
          "r"(__float_as_uint(a[2])), "r"(__float_as_uint(a[3])),
          "r"(__float_as_uint(b[0])), "r"(__float_as_uint(b[1])));
}

// Load one K-chunk (A: 128x32 rows m0.., B: 32x128) into registers (tf32-rounded)
__device__ __forceinline__ void load_chunk(
    const float* __restrict__ A, size_t lda, bool gather, int m0,
    const float* __restrict__ B, int ldb, int k0,
    float4 (&ar)[4], float4 (&br)[4], int tid)
{
    const int ia = tid >> 3;
    const int kc4 = (tid & 7) * 4;
#pragma unroll
    for (int p = 0; p < 4; p++) {
        const int r = m0 + ia + 32 * p;
        size_t off;
        if (gather)
            off = (size_t)(r & 31) * (NLOC * CDIM) + (size_t)(r >> 5) * CDIM;
        else
            off = (size_t)r * lda;
        float4 v = *(const float4*)&A[off + k0 + kc4];
        cvt4(v);
        ar[p] = v;
    }
    const int kr = tid >> 3;
    const int nb = (tid & 7) * 4;
#pragma unroll
    for (int p = 0; p < 4; p++) {
        float4 v = *(const float4*)&B[(size_t)(k0 + kr) * ldb + nb + 32 * p];
        cvt4(v);
        br[p] = v;
    }
}

__device__ __forceinline__ void stage_chunk(
    float* As, float* Bs, const float4 (&ar)[4], const float4 (&br)[4], int tid)
{
    const int ia = tid >> 3;
    const int kc4 = (tid & 7) * 4;
#pragma unroll
    for (int p = 0; p < 4; p++)
        *(float4*)&As[(ia + 32 * p) * AP + kc4] = ar[p];
    const int kr = tid >> 3;
    const int nb = (tid & 7) * 4;
#pragma unroll
    for (int p = 0; p < 4; p++)
        *(float4*)&Bs[kr * BP + nb + 32 * p] = br[p];
}

__device__ __forceinline__ void compute_chunk(
    const float* __restrict__ As, const float* __restrict__ Bs,
    float acc[4][4][4], int wm, int wn, int g, int t)
{
#pragma unroll
    for (int ks = 0; ks < 4; ks++) {
        const int kk = ks * 8;
        float b[4][2];
#pragma unroll
        for (int nf = 0; nf < 4; nf++) {
            const int n = wn * 32 + nf * 8 + g;
            b[nf][0] = Bs[(kk + t) * BP + n];
            b[nf][1] = Bs[(kk + t + 4) * BP + n];
        }
#pragma unroll
        for (int mf = 0; mf < 4; mf++) {
            const int row = wm * 64 + mf * 16 + g;
            float a[4];
            a[0] = As[row * AP + kk + t];
            a[1] = As[(row + 8) * AP + kk + t];
            a[2] = As[row * AP + kk + t + 4];
            a[3] = As[(row + 8) * AP + kk + t + 4];
#pragma unroll
            for (int nf = 0; nf < 4; nf++)
                mma8(acc[mf][nf], a, b[nf]);
        }
    }
}

template<int NC>
__device__ __forceinline__ void run_gemm(
    const float* __restrict__ A, size_t lda, bool gather, int m0,
    const float* __restrict__ B, int ldb,
    float acc[4][4][4], float* smem, int tid,
    int wm, int wn, int g, int t)
{
#pragma unroll
    for (int i = 0; i < 4; i++)
#pragma unroll
        for (int j = 0; j < 4; j++)
#pragma unroll
            for (int q = 0; q < 4; q++) acc[i][j][q] = 0.0f;

    float* As0 = smem;
    float* Bs0 = smem + ASZ;
    float* As1 = smem + BUFSZ;
    float* Bs1 = smem + BUFSZ + ASZ;

    float4 ar[4], br[4];
    load_chunk(A, lda, gather, m0, B, ldb, 0, ar, br, tid);
    stage_chunk(As0, Bs0, ar, br, tid);
    __syncthreads();

    for (int c = 0; c < NC; c++) {
        const bool more = (c + 1 < NC);
        if (more)
            load_chunk(A, lda, gather, m0, B, ldb, (c + 1) * 32, ar, br, tid);
        const float* Asc = (c & 1) ? As1 : As0;
        const float* Bsc = (c & 1) ? Bs1 : Bs0;
        compute_chunk(Asc, Bsc, acc, wm, wn, g, t);
        if (more) {
            float* Asn = ((c + 1) & 1) ? As1 : As0;
            float* Bsn = ((c + 1) & 1) ? Bs1 : Bs0;
            stage_chunk(Asn, Bsn, ar, br, tid);
        }
        __syncthreads();
    }
}

// ============================================================
// Kernel 1: fused QKV projection (tf32 MMA)
// ============================================================
__global__ __launch_bounds__(256, 2)
void k_qkv(const float* __restrict__ x,
           const float* __restrict__ wq, const float* __restrict__ bq,
           const float* __restrict__ wk, const float* __restrict__ bk,
           const float* __restrict__ wv, const float* __restrict__ bv)
{
    extern __shared__ float smem[];
    const int tid = threadIdx.x;
    const int warp = tid >> 5, lane = tid & 31;
    const int wm = warp >> 2, wn = warp & 3;
    const int g = lane >> 2, t = lane & 3;
    const int m0 = blockIdx.x * 128;
    const int which = blockIdx.y;

    const float* W; const float* BIAS; float* OUT;
    if (which == 0)      { W = wq; BIAS = bq; OUT = g_q; }
    else if (which == 1) { W = wk; BIAS = bk; OUT = g_k; }
    else                 { W = wv; BIAS = bv; OUT = g_v; }

    float acc[4][4][4];
    run_gemm<4>(x, 0, true, m0, W, CDIM, acc, smem, tid, wm, wn, g, t);

#pragma unroll
    for (int nf = 0; nf < 4; nf++) {
        const int col = wn * 32 + nf * 8 + 2 * t;
        const float2 bv2 = *(const float2*)&BIAS[col];
#pragma unroll
        for (int mf = 0; mf < 4; mf++) {
            const int r0 = m0 + wm * 64 + mf * 16 + g;
            float2 o0, o1;
            o0.x = acc[mf][nf][0] + bv2.x; o0.y = acc[mf][nf][1] + bv2.y;
            o1.x = acc[mf][nf][2] + bv2.x; o1.y = acc[mf][nf][3] + bv2.y;
            *(float2*)&OUT[(size_t)r0 * CDIM + col] = o0;
            *(float2*)&OUT[(size_t)(r0 + 8) * CDIM + col] = o1;
        }
    }
}

// ============================================================
// Kernel 2: attention per location n + residual + LayerNorm1
// ============================================================
#define PAD 132
__global__ __launch_bounds__(256)
void k_attn(const float* __restrict__ x,
            const float* __restrict__ ln1g, const float* __restrict__ ln1b)
{
    __shared__ float t0[SEQ][PAD];
    __shared__ float t1[SEQ][PAD];
    __shared__ float sinT[SEQ][8];
    __shared__ float cosT[SEQ][8];

    const int n = blockIdx.x;
    const int tid = threadIdx.x;

    for (int idx = tid; idx < SEQ * 8; idx += 256) {
        const int s = idx >> 3, j = idx & 7;
        const float ang = powf(10000.0f, -(float)j / 7.0f);
        float sv, cv;
        sincosf((float)s * ang, &sv, &cv);
        sinT[s][j] = sv;
        cosT[s][j] = cv;
    }
    __syncthreads();

    const size_t base = (size_t)n * SEQ * CDIM;

    for (int idx = tid; idx < SEQ * CDIM; idx += 256) {
        const int s = idx >> 7, c = idx & 127;
        const int h = c >> 4, hd = c & 15;
        const int pc = (hd < 8) ? (h * 16 + 2 * hd + 1) : (h * 16 + 2 * hd - 16);
        const float sgn = (hd < 8) ? -1.0f : 1.0f;
        const float sv = sinT[s][hd >> 1];
        const float cv = cosT[s][hd >> 1];
        {
            const float tq = g_q[base + (size_t)s * CDIM + c];
            const float p = g_q[base + (size_t)s * CDIM + pc];
            t0[s][c] = tq * cv + sgn * p * sv;
        }
        {
            const float tk = g_k[base + (size_t)s * CDIM + c];
            const float p = g_k[base + (size_t)s * CDIM + pc];
            t1[s][c] = tk * cv + sgn * p * sv;
        }
    }
    __syncthreads();

    const int warp = tid >> 5;
    const int lane = tid & 31;
    float p[SEQ];
    float inv = 0.0f;
    {
        const int h = warp;
        float qr[HD];
#pragma unroll
        for (int d4 = 0; d4 < 4; d4++)
            *(float4*)&qr[d4 * 4] = *(const float4*)&t0[lane][h * 16 + d4 * 4];
        const float decay = log1pf(-exp2f(-(1.0f + 3.0f * (float)h / 8.0f)));
        float mx = -1e30f;
#pragma unroll
        for (int j = 0; j < SEQ; j++) {
            float kr[HD];
#pragma unroll
            for (int d4 = 0; d4 < 4; d4++)
                *(float4*)&kr[d4 * 4] = *(const float4*)&t1[j][h * 16 + d4 * 4];
            float dot = 0.0f;
#pragma unroll
            for (int d = 0; d < HD; d++) dot += qr[d] * kr[d];
            dot += fabsf((float)(lane - j)) * decay;
            p[j] = dot;
            mx = fmaxf(mx, dot);
        }
        float sum = 0.0f;
#pragma unroll
        for (int j = 0; j < SEQ; j++) { p[j] = expf(p[j] - mx); sum += p[j]; }
        inv = 1.0f / sum;
    }
    __syncthreads();

    for (int idx = tid; idx < SEQ * CDIM; idx += 256) {
        const int s = idx >> 7, c = idx & 127;
        t0[s][c] = g_v[base + (size_t)s * CDIM + c];
    }
    __syncthreads();

    {
        float o[HD];
#pragma unroll
        for (int d = 0; d < HD; d++) o[d] = 0.0f;
#pragma unroll
        for (int j = 0; j < SEQ; j++) {
            float vr[HD];
#pragma unroll
            for (int d4 = 0; d4 < 4; d4++)
                *(float4*)&vr[d4 * 4] = *(const float4*)&t0[j][warp * 16 + d4 * 4];
#pragma unroll
            for (int d = 0; d < HD; d++) o[d] += p[j] * vr[d];
        }
#pragma unroll
        for (int d4 = 0; d4 < 4; d4++) {
            float4 ov;
            ov.x = o[d4 * 4 + 0] * inv; ov.y = o[d4 * 4 + 1] * inv;
            ov.z = o[d4 * 4 + 2] * inv; ov.w = o[d4 * 4 + 3] * inv;
            *(float4*)&t1[lane][warp * 16 + d4 * 4] = ov;
        }
    }
    __syncthreads();

#pragma unroll
    for (int rr = 0; rr < 4; rr++) {
        const int s = warp * 4 + rr;
        const int c = lane * 4;
        float4 ov = *(const float4*)&t1[s][c];
        float4 xv = *(const float4*)&x[(size_t)s * NLOC * CDIM + (size_t)n * CDIM + c];
        float v0 = ov.x + xv.x, v1 = ov.y + xv.y, v2 = ov.z + xv.z, v3 = ov.w + xv.w;
        float sum = v0 + v1 + v2 + v3;
        float sq  = v0 * v0 + v1 * v1 + v2 * v2 + v3 * v3;
#pragma unroll
        for (int off = 16; off > 0; off >>= 1) {
            sum += __shfl_xor_sync(0xffffffffu, sum, off);
            sq  += __shfl_xor_sync(0xffffffffu, sq,  off);
        }
        const float mu  = sum * (1.0f / 128.0f);
        const float var = sq * (1.0f / 128.0f) - mu * mu;
        const float wn  = rsqrtf(var + 1e-5f);
        float4 g4 = *(const float4*)&ln1g[c];
        float4 b4 = *(const float4*)&ln1b[c];
        float4 o;
        o.x = (v0 - mu) * wn * g4.x + b4.x;
        o.y = (v1 - mu) * wn * g4.y + b4.y;
        o.z = (v2 - mu) * wn * g4.z + b4.z;
        o.w = (v3 - mu) * wn * g4.w + b4.w;
        *(float4*)&g_x1[base + (size_t)s * CDIM + c] = o;
    }
}

// ============================================================
// Kernel 3: FFN1 H = relu(X1 @ W1 + b1)   (tf32 MMA)
// ============================================================
__global__ __launch_bounds__(256, 2)
void k_ffn1(const float* __restrict__ w1, const float* __restrict__ b1)
{
    extern __shared__ float smem[];
    const int tid = threadIdx.x;
    const int warp = tid >> 5, lane = tid & 31;
    const int wm = warp >> 2, wn = warp & 3;
    const int g = lane >> 2, t = lane & 3;
    const int m0 = blockIdx.x * 128;
    const int bn0 = blockIdx.y * 128;

    float acc[4][4][4];
    run_gemm<4>(g_x1, CDIM, false, m0, w1 + bn0, FFND, acc, smem, tid, wm, wn, g, t);

#pragma unroll
    for (int nf = 0; nf < 4; nf++) {
        const int col = wn * 32 + nf * 8 + 2 * t;
        const float2 bv2 = *(const float2*)&b1[bn0 + col];
#pragma unroll
        for (int mf = 0; mf < 4; mf++) {
            const int r0 = m0 + wm * 64 + mf * 16 + g;
            float2 o0, o1;
            o0.x = fmaxf(acc[mf][nf][0] + bv2.x, 0.0f);
            o0.y = fmaxf(acc[mf][nf][1] + bv2.y, 0.0f);
            o1.x = fmaxf(acc[mf][nf][2] + bv2.x, 0.0f);
            o1.y = fmaxf(acc[mf][nf][3] + bv2.y, 0.0f);
            *(float2*)&g_h[(size_t)r0 * FFND + bn0 + col] = o0;
            *(float2*)&g_h[(size_t)(r0 + 8) * FFND + bn0 + col] = o1;
        }
    }
}

// ============================================================
// Kernel 4: FFN2 + residual + LN2 + transposed output (tf32 MMA)
// ============================================================
#define TP 132
__global__ __launch_bounds__(256, 2)
void k_ffn2(const float* __restrict__ w2, const float* __restrict__ b2,
            const float* __restrict__ ln2g, const float* __restrict__ ln2b,
            float* __restrict__ out)
{
    extern __shared__ float smem[];
    const int tid = threadIdx.x;
    const int warp = tid >> 5, lane = tid & 31;
    const int wm = warp >> 2, wn = warp & 3;
    const int g = lane >> 2, t = lane & 3;
    const int m0 = blockIdx.x * 128;

    float acc[4][4][4];
    run_gemm<16>(g_h, FFND, false, m0, w2, CDIM, acc, smem, tid, wm, wn, g, t);
    // run_gemm ends with __syncthreads(): smem is free to reuse

    // stage (acc + bias) tile to smem: T[128][132]
    float* T = smem;
#pragma unroll
    for (int nf = 0; nf < 4; nf++) {
        const int col = wn * 32 + nf * 8 + 2 * t;
        const float2 bv2 = *(const float2*)&b2[col];
#pragma unroll
        for (int mf = 0; mf < 4; mf++) {
            const int row0 = wm * 64 + mf * 16 + g;
            float2 o0, o1;
            o0.x = acc[mf][nf][0] + bv2.x; o0.y = acc[mf][nf][1] + bv2.y;
            o1.x = acc[mf][nf][2] + bv2.x; o1.y = acc[mf][nf][3] + bv2.y;
            *(float2*)&T[row0 * TP + col] = o0;
            *(float2*)&T[(row0 + 8) * TP + col] = o1;
        }
    }
    __syncthreads();

    // per-row: + residual x1, LayerNorm2, transposed store
#pragma unroll
    for (int rr = 0; rr < 16; rr++) {
        const int row = warp * 16 + rr;
        const int r = m0 + row;
        const int c = lane * 4;
        float4 v = *(const float4*)&T[row * TP + c];
        float4 xv = *(const float4*)&g_x1[(size_t)r * CDIM + c];
        float v0 = v.x + xv.x, v1 = v.y + xv.y, v2 = v.z + xv.z, v3 = v.w + xv.w;
        float sum = v0 + v1 + v2 + v3;
        float sq  = v0 * v0 + v1 * v1 + v2 * v2 + v3 * v3;
#pragma unroll
        for (int off = 16; off > 0; off >>= 1) {
            sum += __shfl_xor_sync(0xffffffffu, sum, off);
            sq  += __shfl_xor_sync(0xffffffffu, sq,  off);
        }
        const float mu  = sum * (1.0f / 128.0f);
        const float var = sq * (1.0f / 128.0f) - mu * mu;
        const float wnr = rsqrtf(var + 1e-5f);
        float4 g4 = *(const float4*)&ln2g[c];
        float4 b4 = *(const float4*)&ln2b[c];
        float4 o;
        o.x = (v0 - mu) * wnr * g4.x + b4.x;
        o.y = (v1 - mu) * wnr * g4.y + b4.y;
        o.z = (v2 - mu) * wnr * g4.z + b4.z;
        o.w = (v3 - mu) * wnr * g4.w + b4.w;
        const int nn = r >> 5;
        const int ss = r & 31;
        *(float4*)&out[(size_t)ss * NLOC * CDIM + (size_t)nn * CDIM + c] = o;
    }
}

// ============================================================
extern "C" void kernel_launch(void* const* d_in, const int* in_sizes, int n_in,
                              void* d_out, int out_size)
{
    (void)in_sizes; (void)n_in; (void)out_size;
    const float* x    = (const float*)d_in[0];
    const float* wq   = (const float*)d_in[1];
    const float* bq   = (const float*)d_in[2];
    const float* wk   = (const float*)d_in[3];
    const float* bk   = (const float*)d_in[4];
    const float* wv   = (const float*)d_in[5];
    const float* bv   = (const float*)d_in[6];
    const float* ln1g = (const float*)d_in[7];
    const float* ln1b = (const float*)d_in[8];
    const float* w1   = (const float*)d_in[9];
    const float* b1   = (const float*)d_in[10];
    const float* w2   = (const float*)d_in[11];
    const float* b2   = (const float*)d_in[12];
    const float* ln2g = (const float*)d_in[13];
    const float* ln2b = (const float*)d_in[14];
    float* out = (float*)d_out;

    cudaFuncSetAttribute(k_qkv,  cudaFuncAttributeMaxDynamicSharedMemorySize, SMEM_BYTES);
    cudaFuncSetAttribute(k_ffn1, cudaFuncAttributeMaxDynamicSharedMemorySize, SMEM_BYTES);
    cudaFuncSetAttribute(k_ffn2, cudaFuncAttributeMaxDynamicSharedMemorySize, SMEM_BYTES);

    dim3 g1(MROWS / 128, 3);
    k_qkv<<<g1, 256, SMEM_BYTES>>>(x, wq, bq, wk, bk, wv, bv);

    k_attn<<<NLOC, 256>>>(x, ln1g, ln1b);

    dim3 g3(MROWS / 128, 4);
    k_ffn1<<<g3, 256, SMEM_BYTES>>>(w1, b1);

    k_ffn2<<<MROWS / 128, 256, SMEM_BYTES>>>(w2, b2, ln2g, ln2b, out);
}

// round 4
// speedup vs baseline: 2.4306x; 1.2689x over previous
#include <cuda_runtime.h>
#include <math.h>

#define NLOC 8192
#define SEQ 32
#define CDIM 128
#define NHEAD 8
#define HD 16
#define MROWS (NLOC*SEQ)   // 262144
#define FFND 512

// -------- scratch (static device globals; no runtime allocation) --------
__device__ float g_x1[(size_t)MROWS * CDIM];  // 128 MB
__device__ float g_h[(size_t)MROWS * FFND];   // 512 MB

// ======================= tf32 helpers =======================
__device__ __forceinline__ float tf32r(float x) {
    unsigned u;
    asm("cvt.rna.tf32.f32 %0, %1;" : "=r"(u) : "f"(x));
    return __uint_as_float(u);
}
__device__ __forceinline__ void cvt4(float4& v) {
    v.x = tf32r(v.x); v.y = tf32r(v.y); v.z = tf32r(v.z); v.w = tf32r(v.w);
}
__device__ __forceinline__ void mma8(float* c, const float* a, const float* b) {
    asm volatile(
        "mma.sync.aligned.m16n8k8.row.col.f32.tf32.tf32.f32 "
        "{%0,%1,%2,%3}, {%4,%5,%6,%7}, {%8,%9}, {%0,%1,%2,%3};"
        : "+f"(c[0]), "+f"(c[1]), "+f"(c[2]), "+f"(c[3])
        : "r"(__float_as_uint(a[0])), "r"(__float_as_uint(a[1])),
          "r"(__float_as_uint(a[2])), "r"(__float_as_uint(a[3])),
          "r"(__float_as_uint(b[0])), "r"(__float_as_uint(b[1])));
}

// ================== 256-thread GEMM machinery (FFN kernels) ==================
// CTA tile 128x128, 8 warps, warp tile 64x32, K chunk 32, double buffered.
#define AP 36
#define BP 136
#define ASZ (128*AP)
#define BSZ (32*BP)
#define BUFSZ (ASZ+BSZ)       // 8960 floats
#define SMEM_FLOATS (2*BUFSZ) // 17920 floats
#define SMEM_BYTES (SMEM_FLOATS*4)

__device__ __forceinline__ void load_chunk(
    const float* __restrict__ A, size_t lda, int m0,
    const float* __restrict__ B, int ldb, int k0,
    float4 (&ar)[4], float4 (&br)[4], int tid)
{
    const int ia = tid >> 1;
    const int kc4 = (tid & 1) * 4;
#pragma unroll
    for (int p = 0; p < 2; p++) {
        // 2 rows apart? keep original mapping: ia covers 0..127 via tid>>1 and p offset
        ;
    }
    // original mapping: ia = tid>>3 (0..31), 4 row-phases of 32
    const int ia2 = tid >> 3;
    const int kc = (tid & 7) * 4;
#pragma unroll
    for (int p = 0; p < 4; p++) {
        const int r = m0 + ia2 + 32 * p;
        float4 v = *(const float4*)&A[(size_t)r * lda + k0 + kc];
        cvt4(v);
        ar[p] = v;
    }
    const int kr = tid >> 3;
    const int nb = (tid & 7) * 4;
#pragma unroll
    for (int p = 0; p < 4; p++) {
        float4 v = *(const float4*)&B[(size_t)(k0 + kr) * ldb + nb + 32 * p];
        cvt4(v);
        br[p] = v;
    }
}

__device__ __forceinline__ void stage_chunk(
    float* As, float* Bs, const float4 (&ar)[4], const float4 (&br)[4], int tid)
{
    const int ia = tid >> 3;
    const int kc = (tid & 7) * 4;
#pragma unroll
    for (int p = 0; p < 4; p++)
        *(float4*)&As[(ia + 32 * p) * AP + kc] = ar[p];
    const int kr = tid >> 3;
    const int nb = (tid & 7) * 4;
#pragma unroll
    for (int p = 0; p < 4; p++)
        *(float4*)&Bs[kr * BP + nb + 32 * p] = br[p];
}

__device__ __forceinline__ void compute_chunk(
    const float* __restrict__ As, const float* __restrict__ Bs,
    float acc[4][4][4], int wm, int wn, int g, int t)
{
#pragma unroll
    for (int ks = 0; ks < 4; ks++) {
        const int kk = ks * 8;
        float b[4][2];
#pragma unroll
        for (int nf = 0; nf < 4; nf++) {
            const int n = wn * 32 + nf * 8 + g;
            b[nf][0] = Bs[(kk + t) * BP + n];
            b[nf][1] = Bs[(kk + t + 4) * BP + n];
        }
#pragma unroll
        for (int mf = 0; mf < 4; mf++) {
            const int row = wm * 64 + mf * 16 + g;
            float a[4];
            a[0] = As[row * AP + kk + t];
            a[1] = As[(row + 8) * AP + kk + t];
            a[2] = As[row * AP + kk + t + 4];
            a[3] = As[(row + 8) * AP + kk + t + 4];
#pragma unroll
            for (int nf = 0; nf < 4; nf++)
                mma8(acc[mf][nf], a, b[nf]);
        }
    }
}

template<int NC>
__device__ __forceinline__ void run_gemm(
    const float* __restrict__ A, size_t lda, int m0,
    const float* __restrict__ B, int ldb,
    float acc[4][4][4], float* smem, int tid,
    int wm, int wn, int g, int t)
{
#pragma unroll
    for (int i = 0; i < 4; i++)
#pragma unroll
        for (int j = 0; j < 4; j++)
#pragma unroll
            for (int q = 0; q < 4; q++) acc[i][j][q] = 0.0f;

    float* As0 = smem;
    float* Bs0 = smem + ASZ;
    float* As1 = smem + BUFSZ;
    float* Bs1 = smem + BUFSZ + ASZ;

    float4 ar[4], br[4];
    load_chunk(A, lda, m0, B, ldb, 0, ar, br, tid);
    stage_chunk(As0, Bs0, ar, br, tid);
    __syncthreads();

    for (int c = 0; c < NC; c++) {
        const bool more = (c + 1 < NC);
        if (more)
            load_chunk(A, lda, m0, B, ldb, (c + 1) * 32, ar, br, tid);
        const float* Asc = (c & 1) ? As1 : As0;
        const float* Bsc = (c & 1) ? Bs1 : Bs0;
        compute_chunk(Asc, Bsc, acc, wm, wn, g, t);
        if (more) {
            float* Asn = ((c + 1) & 1) ? As1 : As0;
            float* Bsn = ((c + 1) & 1) ? Bs1 : Bs0;
            stage_chunk(Asn, Bsn, ar, br, tid);
        }
        __syncthreads();
    }
}

// ============================================================
// Kernel 1 (FUSED): QKV projection + rotary + attention + residual + LN1
// 512 threads, 16 warps, warp tile 32x32. 1 CTA = 128 rows = 4 locations.
// smem: [stage 17920][Kbuf 128*132][Vbuf 128*132]; Qbuf aliases stage.
// ============================================================
#define FP 132
#define F_STAGE_FLOATS 17920
#define F_KBUF (F_STAGE_FLOATS)
#define F_VBUF (F_KBUF + 128*FP)
#define F_SMEM_FLOATS (F_VBUF + 128*FP)       // 51712 floats
#define F_SMEM_BYTES (F_SMEM_FLOATS*4)        // 206848 bytes

// 512-thread chunk load (A gathered from x), CTA tile 128x128, K chunk 32
__device__ __forceinline__ void f_load_chunk(
    const float* __restrict__ x, int m0,
    const float* __restrict__ B, int k0,
    float4 (&ar)[2], float4 (&br)[2], int tid)
{
    const int ia = tid >> 2;            // 0..127
    const int kc = (tid & 3) * 8;       // 0,8,16,24
    const int r = m0 + ia;
    const size_t off = (size_t)(r & 31) * (NLOC * CDIM) + (size_t)(r >> 5) * CDIM;
#pragma unroll
    for (int p = 0; p < 2; p++) {
        float4 v = *(const float4*)&x[off + k0 + kc + 4 * p];
        cvt4(v);
        ar[p] = v;
    }
    const int kr = tid >> 4;            // 0..31
    const int nb = (tid & 15) * 8;      // 0..120
#pragma unroll
    for (int p = 0; p < 2; p++) {
        float4 v = *(const float4*)&B[(size_t)(k0 + kr) * CDIM + nb + 4 * p];
        cvt4(v);
        br[p] = v;
    }
}

__device__ __forceinline__ void f_stage_chunk(
    float* As, float* Bs, const float4 (&ar)[2], const float4 (&br)[2], int tid)
{
    const int ia = tid >> 2;
    const int kc = (tid & 3) * 8;
#pragma unroll
    for (int p = 0; p < 2; p++)
        *(float4*)&As[ia * AP + kc + 4 * p] = ar[p];
    const int kr = tid >> 4;
    const int nb = (tid & 15) * 8;
#pragma unroll
    for (int p = 0; p < 2; p++)
        *(float4*)&Bs[kr * BP + nb + 4 * p] = br[p];
}

__device__ __forceinline__ void f_compute_chunk(
    const float* __restrict__ As, const float* __restrict__ Bs,
    float acc[2][4][4], int wm, int wn, int g, int t)
{
#pragma unroll
    for (int ks = 0; ks < 4; ks++) {
        const int kk = ks * 8;
        float b[4][2];
#pragma unroll
        for (int nf = 0; nf < 4; nf++) {
            const int n = wn * 32 + nf * 8 + g;
            b[nf][0] = Bs[(kk + t) * BP + n];
            b[nf][1] = Bs[(kk + t + 4) * BP + n];
        }
#pragma unroll
        for (int mf = 0; mf < 2; mf++) {
            const int row = wm * 32 + mf * 16 + g;
            float a[4];
            a[0] = As[row * AP + kk + t];
            a[1] = As[(row + 8) * AP + kk + t];
            a[2] = As[row * AP + kk + t + 4];
            a[3] = As[(row + 8) * AP + kk + t + 4];
#pragma unroll
            for (int nf = 0; nf < 4; nf++)
                mma8(acc[mf][nf], a, b[nf]);
        }
    }
}

// full GEMM (K=128, 4 chunks) for the fused kernel; result -> dst smem tile
__device__ __forceinline__ void f_gemm_to_smem(
    const float* __restrict__ x, int m0,
    const float* __restrict__ W, const float* __restrict__ BIAS,
    float* smem, float* dst, int tid, int wm, int wn, int g, int t)
{
    float acc[2][4][4];
#pragma unroll
    for (int i = 0; i < 2; i++)
#pragma unroll
        for (int j = 0; j < 4; j++)
#pragma unroll
            for (int q = 0; q < 4; q++) acc[i][j][q] = 0.0f;

    float* As0 = smem;
    float* Bs0 = smem + ASZ;
    float* As1 = smem + BUFSZ;
    float* Bs1 = smem + BUFSZ + ASZ;

    float4 ar[2], br[2];
    f_load_chunk(x, m0, W, 0, ar, br, tid);
    f_stage_chunk(As0, Bs0, ar, br, tid);
    __syncthreads();

    for (int c = 0; c < 4; c++) {
        const bool more = (c + 1 < 4);
        if (more)
            f_load_chunk(x, m0, W, (c + 1) * 32, ar, br, tid);
        const float* Asc = (c & 1) ? As1 : As0;
        const float* Bsc = (c & 1) ? Bs1 : Bs0;
        f_compute_chunk(Asc, Bsc, acc, wm, wn, g, t);
        if (more) {
            float* Asn = ((c + 1) & 1) ? As1 : As0;
            float* Bsn = ((c + 1) & 1) ? Bs1 : Bs0;
            f_stage_chunk(Asn, Bsn, ar, br, tid);
        }
        __syncthreads();
    }

    // epilogue: acc + bias -> dst[row][col], pitch FP
#pragma unroll
    for (int nf = 0; nf < 4; nf++) {
        const int col = wn * 32 + nf * 8 + 2 * t;
        const float2 bv2 = *(const float2*)&BIAS[col];
#pragma unroll
        for (int mf = 0; mf < 2; mf++) {
            const int row0 = wm * 32 + mf * 16 + g;
            float2 o0, o1;
            o0.x = acc[mf][nf][0] + bv2.x; o0.y = acc[mf][nf][1] + bv2.y;
            o1.x = acc[mf][nf][2] + bv2.x; o1.y = acc[mf][nf][3] + bv2.y;
            *(float2*)&dst[row0 * FP + col] = o0;
            *(float2*)&dst[(row0 + 8) * FP + col] = o1;
        }
    }
}

__global__ __launch_bounds__(512, 1)
void k_fused_attn(const float* __restrict__ x,
                  const float* __restrict__ wq, const float* __restrict__ bq,
                  const float* __restrict__ wk, const float* __restrict__ bk,
                  const float* __restrict__ wv, const float* __restrict__ bv,
                  const float* __restrict__ ln1g, const float* __restrict__ ln1b)
{
    extern __shared__ float smem[];
    __shared__ float sinT[SEQ][8];
    __shared__ float cosT[SEQ][8];

    float* stage = smem;
    float* Kbuf  = smem + F_KBUF;
    float* Vbuf  = smem + F_VBUF;
    float* Qbuf  = stage;   // aliases staging; used only after all GEMMs done

    const int tid = threadIdx.x;
    const int warp = tid >> 5, lane = tid & 31;
    const int wm = warp >> 2, wn = warp & 3;
    const int g = lane >> 2, t = lane & 3;
    const int m0 = blockIdx.x * 128;

    // sin/cos table
    if (tid < SEQ * 8) {
        const int s = tid >> 3, j = tid & 7;
        const float ang = powf(10000.0f, -(float)j / 7.0f);
        float sv, cv;
        sincosf((float)s * ang, &sv, &cv);
        sinT[s][j] = sv;
        cosT[s][j] = cv;
    }
    // (first __syncthreads inside f_gemm_to_smem covers visibility)

    // GEMMs: K -> Kbuf, V -> Vbuf, Q -> Qbuf (staging area, dead after GEMMs)
    f_gemm_to_smem(x, m0, wk, bk, stage, Kbuf, tid, wm, wn, g, t);
    f_gemm_to_smem(x, m0, wv, bv, stage, Vbuf, tid, wm, wn, g, t);
    f_gemm_to_smem(x, m0, wq, bq, stage, Qbuf, tid, wm, wn, g, t);
    __syncthreads();

    // In-place rotary on Qbuf and Kbuf: task = (row, head), self-contained.
    // 128 rows x 8 heads = 1024 tasks, 2 per thread.
#pragma unroll
    for (int task = tid; task < 128 * NHEAD; task += 512) {
        const int row = task >> 3, h = task & 7;
        const int s = row & 31;
        float tq[HD], tk[HD];
#pragma unroll
        for (int d4 = 0; d4 < 4; d4++) {
            *(float4*)&tq[d4 * 4] = *(const float4*)&Qbuf[row * FP + h * 16 + d4 * 4];
            *(float4*)&tk[d4 * 4] = *(const float4*)&Kbuf[row * FP + h * 16 + d4 * 4];
        }
        float rq[HD], rk[HD];
#pragma unroll
        for (int d = 0; d < HD; d++) {
            const float sv = sinT[s][d >> 1];
            const float cv = cosT[s][d >> 1];
            const int pc = (d < 8) ? (2 * d + 1) : (2 * d - 16);
            const float sgn = (d < 8) ? -1.0f : 1.0f;
            rq[d] = tq[d] * cv + sgn * tq[pc] * sv;
            rk[d] = tk[d] * cv + sgn * tk[pc] * sv;
        }
#pragma unroll
        for (int d4 = 0; d4 < 4; d4++) {
            *(float4*)&Qbuf[row * FP + h * 16 + d4 * 4] = *(const float4*)&rq[d4 * 4];
            *(float4*)&Kbuf[row * FP + h * 16 + d4 * 4] = *(const float4*)&rk[d4 * 4];
        }
    }
    __syncthreads();

    // Attention: warp w handles head h = w&7, locations {(w>>3)*2 + step}.
    const int h = warp & 7;
    const float decay = log1pf(-exp2f(-(1.0f + 3.0f * (float)h / 8.0f)));

#pragma unroll
    for (int step = 0; step < 2; step++) {
        const int l = (warp >> 3) * 2 + step;
        const int qrow = l * 32 + lane;   // lane = query index i

        float qr[HD];
#pragma unroll
        for (int d4 = 0; d4 < 4; d4++)
            *(float4*)&qr[d4 * 4] = *(const float4*)&Qbuf[qrow * FP + h * 16 + d4 * 4];

        float p[SEQ];
        float mx = -1e30f;
#pragma unroll
        for (int j = 0; j < SEQ; j++) {
            float kr[HD];
#pragma unroll
            for (int d4 = 0; d4 < 4; d4++)
                *(float4*)&kr[d4 * 4] = *(const float4*)&Kbuf[(l * 32 + j) * FP + h * 16 + d4 * 4];
            float dot = 0.0f;
#pragma unroll
            for (int d = 0; d < HD; d++) dot += qr[d] * kr[d];
            dot += fabsf((float)(lane - j)) * decay;
            p[j] = dot;
            mx = fmaxf(mx, dot);
        }
        float sum = 0.0f;
#pragma unroll
        for (int j = 0; j < SEQ; j++) { p[j] = expf(p[j] - mx); sum += p[j]; }
        const float inv = 1.0f / sum;

        __syncthreads();  // all warps done reading Q rows for this step

        float o[HD];
#pragma unroll
        for (int d = 0; d < HD; d++) o[d] = 0.0f;
#pragma unroll
        for (int j = 0; j < SEQ; j++) {
            float vr[HD];
#pragma unroll
            for (int d4 = 0; d4 < 4; d4++)
                *(float4*)&vr[d4 * 4] = *(const float4*)&Vbuf[(l * 32 + j) * FP + h * 16 + d4 * 4];
#pragma unroll
            for (int d = 0; d < HD; d++) o[d] += p[j] * vr[d];
        }
#pragma unroll
        for (int d4 = 0; d4 < 4; d4++) {
            float4 ov;
            ov.x = o[d4 * 4 + 0] * inv; ov.y = o[d4 * 4 + 1] * inv;
            ov.z = o[d4 * 4 + 2] * inv; ov.w = o[d4 * 4 + 3] * inv;
            *(float4*)&Qbuf[qrow * FP + h * 16 + d4 * 4] = ov;   // O overwrites Q
        }
    }
    __syncthreads();

    // residual + LN1 -> g_x1 ; 16 warps x 8 rows
#pragma unroll
    for (int rr = 0; rr < 8; rr++) {
        const int row = warp * 8 + rr;
        const int r = m0 + row;
        const int c = lane * 4;
        float4 ov = *(const float4*)&Qbuf[row * FP + c];
        float4 xv = *(const float4*)&x[(size_t)(r & 31) * (NLOC * CDIM) + (size_t)(r >> 5) * CDIM + c];
        float v0 = ov.x + xv.x, v1 = ov.y + xv.y, v2 = ov.z + xv.z, v3 = ov.w + xv.w;
        float sum = v0 + v1 + v2 + v3;
        float sq  = v0 * v0 + v1 * v1 + v2 * v2 + v3 * v3;
#pragma unroll
        for (int off = 16; off > 0; off >>= 1) {
            sum += __shfl_xor_sync(0xffffffffu, sum, off);
            sq  += __shfl_xor_sync(0xffffffffu, sq,  off);
        }
        const float mu  = sum * (1.0f / 128.0f);
        const float var = sq * (1.0f / 128.0f) - mu * mu;
        const float wnr = rsqrtf(var + 1e-5f);
        float4 g4 = *(const float4*)&ln1g[c];
        float4 b4 = *(const float4*)&ln1b[c];
        float4 o;
        o.x = (v0 - mu) * wnr * g4.x + b4.x;
        o.y = (v1 - mu) * wnr * g4.y + b4.y;
        o.z = (v2 - mu) * wnr * g4.z + b4.z;
        o.w = (v3 - mu) * wnr * g4.w + b4.w;
        *(float4*)&g_x1[(size_t)r * CDIM + c] = o;
    }
}

// ============================================================
// Kernel 3: FFN1 H = relu(X1 @ W1 + b1)   (tf32 MMA, 256 thr)
// ============================================================
__global__ __launch_bounds__(256, 2)
void k_ffn1(const float* __restrict__ w1, const float* __restrict__ b1)
{
    extern __shared__ float smem[];
    const int tid = threadIdx.x;
    const int warp = tid >> 5, lane = tid & 31;
    const int wm = warp >> 2, wn = warp & 3;
    const int g = lane >> 2, t = lane & 3;
    const int m0 = blockIdx.x * 128;
    const int bn0 = blockIdx.y * 128;

    float acc[4][4][4];
    run_gemm<4>(g_x1, CDIM, m0, w1 + bn0, FFND, acc, smem, tid, wm, wn, g, t);

#pragma unroll
    for (int nf = 0; nf < 4; nf++) {
        const int col = wn * 32 + nf * 8 + 2 * t;
        const float2 bv2 = *(const float2*)&b1[bn0 + col];
#pragma unroll
        for (int mf = 0; mf < 4; mf++) {
            const int r0 = m0 + wm * 64 + mf * 16 + g;
            float2 o0, o1;
            o0.x = fmaxf(acc[mf][nf][0] + bv2.x, 0.0f);
            o0.y = fmaxf(acc[mf][nf][1] + bv2.y, 0.0f);
            o1.x = fmaxf(acc[mf][nf][2] + bv2.x, 0.0f);
            o1.y = fmaxf(acc[mf][nf][3] + bv2.y, 0.0f);
            *(float2*)&g_h[(size_t)r0 * FFND + bn0 + col] = o0;
            *(float2*)&g_h[(size_t)(r0 + 8) * FFND + bn0 + col] = o1;
        }
    }
}

// ============================================================
// Kernel 4: FFN2 + residual + LN2 + transposed output (tf32 MMA)
// ============================================================
#define TP 132
__global__ __launch_bounds__(256, 2)
void k_ffn2(const float* __restrict__ w2, const float* __restrict__ b2,
            const float* __restrict__ ln2g, const float* __restrict__ ln2b,
            float* __restrict__ out)
{
    extern __shared__ float smem[];
    const int tid = threadIdx.x;
    const int warp = tid >> 5, lane = tid & 31;
    const int wm = warp >> 2, wn = warp & 3;
    const int g = lane >> 2, t = lane & 3;
    const int m0 = blockIdx.x * 128;

    float acc[4][4][4];
    run_gemm<16>(g_h, FFND, m0, w2, CDIM, acc, smem, tid, wm, wn, g, t);

    float* T = smem;
#pragma unroll
    for (int nf = 0; nf < 4; nf++) {
        const int col = wn * 32 + nf * 8 + 2 * t;
        const float2 bv2 = *(const float2*)&b2[col];
#pragma unroll
        for (int mf = 0; mf < 4; mf++) {
            const int row0 = wm * 64 + mf * 16 + g;
            float2 o0, o1;
            o0.x = acc[mf][nf][0] + bv2.x; o0.y = acc[mf][nf][1] + bv2.y;
            o1.x = acc[mf][nf][2] + bv2.x; o1.y = acc[mf][nf][3] + bv2.y;
            *(float2*)&T[row0 * TP + col] = o0;
            *(float2*)&T[(row0 + 8) * TP + col] = o1;
        }
    }
    __syncthreads();

#pragma unroll
    for (int rr = 0; rr < 16; rr++) {
        const int row = warp * 16 + rr;
        const int r = m0 + row;
        const int c = lane * 4;
        float4 v = *(const float4*)&T[row * TP + c];
        float4 xv = *(const float4*)&g_x1[(size_t)r * CDIM + c];
        float v0 = v.x + xv.x, v1 = v.y + xv.y, v2 = v.z + xv.z, v3 = v.w + xv.w;
        float sum = v0 + v1 + v2 + v3;
        float sq  = v0 * v0 + v1 * v1 + v2 * v2 + v3 * v3;
#pragma unroll
        for (int off = 16; off > 0; off >>= 1) {
            sum += __shfl_xor_sync(0xffffffffu, sum, off);
            sq  += __shfl_xor_sync(0xffffffffu, sq,  off);
        }
        const float mu  = sum * (1.0f / 128.0f);
        const float var = sq * (1.0f / 128.0f) - mu * mu;
        const float wnr = rsqrtf(var + 1e-5f);
        float4 g4 = *(const float4*)&ln2g[c];
        float4 b4 = *(const float4*)&ln2b[c];
        float4 o;
        o.x = (v0 - mu) * wnr * g4.x + b4.x;
        o.y = (v1 - mu) * wnr * g4.y + b4.y;
        o.z = (v2 - mu) * wnr * g4.z + b4.z;
        o.w = (v3 - mu) * wnr * g4.w + b4.w;
        const int nn = r >> 5;
        const int ss = r & 31;
        *(float4*)&out[(size_t)ss * NLOC * CDIM + (size_t)nn * CDIM + c] = o;
    }
}

// ============================================================
extern "C" void kernel_launch(void* const* d_in, const int* in_sizes, int n_in,
                              void* d_out, int out_size)
{
    (void)in_sizes; (void)n_in; (void)out_size;
    const float* x    = (const float*)d_in[0];
    const float* wq   = (const float*)d_in[1];
    const float* bq   = (const float*)d_in[2];
    const float* wk   = (const float*)d_in[3];
    const float* bk   = (const float*)d_in[4];
    const float* wv   = (const float*)d_in[5];
    const float* bv   = (const float*)d_in[6];
    const float* ln1g = (const float*)d_in[7];
    const float* ln1b = (const float*)d_in[8];
    const float* w1   = (const float*)d_in[9];
    const float* b1   = (const float*)d_in[10];
    const float* w2   = (const float*)d_in[11];
    const float* b2   = (const float*)d_in[12];
    const float* ln2g = (const float*)d_in[13];
    const float* ln2b = (const float*)d_in[14];
    float* out = (float*)d_out;

    cudaFuncSetAttribute(k_fused_attn, cudaFuncAttributeMaxDynamicSharedMemorySize, F_SMEM_BYTES);
    cudaFuncSetAttribute(k_ffn1, cudaFuncAttributeMaxDynamicSharedMemorySize, SMEM_BYTES);
    cudaFuncSetAttribute(k_ffn2, cudaFuncAttributeMaxDynamicSharedMemorySize, SMEM_BYTES);

    k_fused_attn<<<MROWS / 128, 512, F_SMEM_BYTES>>>(x, wq, bq, wk, bk, wv, bv, ln1g, ln1b);

    dim3 g3(MROWS / 128, 4);
    k_ffn1<<<g3, 256, SMEM_BYTES>>>(w1, b1);

    k_ffn2<<<MROWS / 128, 256, SMEM_BYTES>>>(w2, b2, ln2g, ln2b, out);
}

// round 5
// speedup vs baseline: 2.8530x; 1.1738x over previous
#include <cuda_runtime.h>
#include <math.h>

#define NLOC 8192
#define SEQ 32
#define CDIM 128
#define NHEAD 8
#define HD 16
#define MROWS (NLOC*SEQ)   // 262144
#define FFND 512

// -------- scratch (static device globals; no runtime allocation) --------
__device__ float g_x1[(size_t)MROWS * CDIM];  // 128 MB
__device__ float g_h[(size_t)MROWS * FFND];   // 512 MB

// ======================= mma / cp.async helpers =======================
__device__ __forceinline__ void mma8(float* c, const float* a, const float* b) {
    asm volatile(
        "mma.sync.aligned.m16n8k8.row.col.f32.tf32.tf32.f32 "
        "{%0,%1,%2,%3}, {%4,%5,%6,%7}, {%8,%9}, {%0,%1,%2,%3};"
        : "+f"(c[0]), "+f"(c[1]), "+f"(c[2]), "+f"(c[3])
        : "r"(__float_as_uint(a[0])), "r"(__float_as_uint(a[1])),
          "r"(__float_as_uint(a[2])), "r"(__float_as_uint(a[3])),
          "r"(__float_as_uint(b[0])), "r"(__float_as_uint(b[1])));
}

__device__ __forceinline__ void cp16(void* s, const void* g) {
    unsigned saddr = (unsigned)__cvta_generic_to_shared(s);
    asm volatile("cp.async.cg.shared.global [%0], [%1], 16;" :: "r"(saddr), "l"(g));
}
__device__ __forceinline__ void cp_commit() {
    asm volatile("cp.async.commit_group;");
}
template<int N>
__device__ __forceinline__ void cp_wait() {
    asm volatile("cp.async.wait_group %0;" :: "n"(N));
}

// packed f32x2
typedef unsigned long long u64t;
__device__ __forceinline__ u64t pk2(float lo, float hi) {
    u64t r; asm("mov.b64 %0,{%1,%2};" : "=l"(r) : "f"(lo), "f"(hi)); return r;
}
__device__ __forceinline__ void upk2(u64t v, float& lo, float& hi) {
    asm("mov.b64 {%0,%1},%2;" : "=f"(lo), "=f"(hi) : "l"(v));
}
__device__ __forceinline__ void fma2(u64t& d, u64t a, u64t b) {
    asm("fma.rn.f32x2 %0,%1,%2,%0;" : "+l"(d) : "l"(a), "l"(b));
}

// ================== 256-thread GEMM machinery (FFN kernels) ==================
// CTA tile 128x128, 8 warps, warp tile 64x32, K chunk 32, 3-stage cp.async.
#define AP 36
#define BP 136
#define ASZ (128*AP)
#define BSZ (32*BP)
#define BUFSZ (ASZ+BSZ)          // 8960 floats per stage
#define G3_SMEM_FLOATS (3*BUFSZ) // 26880 floats
#define G3_SMEM_BYTES (G3_SMEM_FLOATS*4)   // 107520 B

__device__ __forceinline__ void copy_chunk_256(
    const float* __restrict__ A, size_t lda, int m0,
    const float* __restrict__ B, int ldb, int k0,
    float* As, float* Bs, int tid)
{
    const int ia = tid >> 3;            // 0..31
    const int kc = (tid & 7) * 4;       // 0..28
#pragma unroll
    for (int p = 0; p < 4; p++)
        cp16(&As[(ia + 32 * p) * AP + kc],
             &A[(size_t)(m0 + ia + 32 * p) * lda + k0 + kc]);
    const int nb = (tid & 7) * 4;
#pragma unroll
    for (int p = 0; p < 4; p++)
        cp16(&Bs[ia * BP + nb + 32 * p],
             &B[(size_t)(k0 + ia) * ldb + nb + 32 * p]);
    cp_commit();
}

__device__ __forceinline__ void compute_chunk(
    const float* __restrict__ As, const float* __restrict__ Bs,
    float acc[4][4][4], int wm, int wn, int g, int t)
{
#pragma unroll
    for (int ks = 0; ks < 4; ks++) {
        const int kk = ks * 8;
        float b[4][2];
#pragma unroll
        for (int nf = 0; nf < 4; nf++) {
            const int n = wn * 32 + nf * 8 + g;
            b[nf][0] = Bs[(kk + t) * BP + n];
            b[nf][1] = Bs[(kk + t + 4) * BP + n];
        }
#pragma unroll
        for (int mf = 0; mf < 4; mf++) {
            const int row = wm * 64 + mf * 16 + g;
            float a[4];
            a[0] = As[row * AP + kk + t];
            a[1] = As[(row + 8) * AP + kk + t];
            a[2] = As[row * AP + kk + t + 4];
            a[3] = As[(row + 8) * AP + kk + t + 4];
#pragma unroll
            for (int nf = 0; nf < 4; nf++)
                mma8(acc[mf][nf], a, b[nf]);
        }
    }
}

template<int NC>
__device__ __forceinline__ void run_gemm(
    const float* __restrict__ A, size_t lda, int m0,
    const float* __restrict__ B, int ldb,
    float acc[4][4][4], float* smem, int tid,
    int wm, int wn, int g, int t)
{
#pragma unroll
    for (int i = 0; i < 4; i++)
#pragma unroll
        for (int j = 0; j < 4; j++)
#pragma unroll
            for (int q = 0; q < 4; q++) acc[i][j][q] = 0.0f;

    copy_chunk_256(A, lda, m0, B, ldb, 0, smem, smem + ASZ, tid);
    if (NC > 1)
        copy_chunk_256(A, lda, m0, B, ldb, 32, smem + BUFSZ, smem + BUFSZ + ASZ, tid);
    cp_wait<(NC > 1) ? 1 : 0>();
    __syncthreads();

    int bc = 0;                 // buffer of chunk c (c % 3)
#pragma unroll 1
    for (int c = 0; c < NC; c++) {
        const float* As = smem + bc * BUFSZ;
        const float* Bs = As + ASZ;
        compute_chunk(As, Bs, acc, wm, wn, g, t);
        __syncthreads();
        if (c + 2 < NC) {
            int bl = bc + 2; if (bl >= 3) bl -= 3;
            float* Ad = smem + bl * BUFSZ;
            copy_chunk_256(A, lda, m0, B, ldb, (c + 2) * 32, Ad, Ad + ASZ, tid);
        }
        if (c + 1 < NC) {
            if (c + 2 < NC) cp_wait<1>(); else cp_wait<0>();
        }
        __syncthreads();
        if (++bc == 3) bc = 0;
    }
}

// ============================================================
// Kernel 1 (FUSED): QKV projection + rotary + attention + residual + LN1
// 512 threads, 16 warps, warp tile 32x32. 1 CTA = 128 rows = 4 locations.
// smem: [stage 2*BUFSZ][Kbuf 128*132][Vbuf 128*132]; Qbuf aliases stage.
// ============================================================
#define FP 132
#define F_STAGE_FLOATS (2*BUFSZ)              // 17920
#define F_KBUF (F_STAGE_FLOATS)
#define F_VBUF (F_KBUF + 128*FP)
#define F_SMEM_FLOATS (F_VBUF + 128*FP)       // 51712 floats
#define F_SMEM_BYTES (F_SMEM_FLOATS*4)        // 206848 bytes

__device__ __forceinline__ void f_copy_chunk(
    const float* __restrict__ x, int m0,
    const float* __restrict__ B, int k0,
    float* As, float* Bs, int tid)
{
    const int ia = tid >> 2;            // 0..127
    const int kc = (tid & 3) * 8;       // 0,8,16,24
    const int r = m0 + ia;
    const size_t off = (size_t)(r & 31) * (NLOC * CDIM) + (size_t)(r >> 5) * CDIM;
    cp16(&As[ia * AP + kc],     &x[off + k0 + kc]);
    cp16(&As[ia * AP + kc + 4], &x[off + k0 + kc + 4]);
    const int kr = tid >> 4;            // 0..31
    const int nb = (tid & 15) * 8;      // 0..120
    cp16(&Bs[kr * BP + nb],     &B[(size_t)(k0 + kr) * CDIM + nb]);
    cp16(&Bs[kr * BP + nb + 4], &B[(size_t)(k0 + kr) * CDIM + nb + 4]);
    cp_commit();
}

__device__ __forceinline__ void f_compute_chunk(
    const float* __restrict__ As, const float* __restrict__ Bs,
    float acc[2][4][4], int wm, int wn, int g, int t)
{
#pragma unroll
    for (int ks = 0; ks < 4; ks++) {
        const int kk = ks * 8;
        float b[4][2];
#pragma unroll
        for (int nf = 0; nf < 4; nf++) {
            const int n = wn * 32 + nf * 8 + g;
            b[nf][0] = Bs[(kk + t) * BP + n];
            b[nf][1] = Bs[(kk + t + 4) * BP + n];
        }
#pragma unroll
        for (int mf = 0; mf < 2; mf++) {
            const int row = wm * 32 + mf * 16 + g;
            float a[4];
            a[0] = As[row * AP + kk + t];
            a[1] = As[(row + 8) * AP + kk + t];
            a[2] = As[row * AP + kk + t + 4];
            a[3] = As[(row + 8) * AP + kk + t + 4];
#pragma unroll
            for (int nf = 0; nf < 4; nf++)
                mma8(acc[mf][nf], a, b[nf]);
        }
    }
}

// full GEMM (K=128, 4 chunks, 2-stage cp.async); result+bias -> dst smem tile
__device__ __forceinline__ void f_gemm_to_smem(
    const float* __restrict__ x, int m0,
    const float* __restrict__ W, const float* __restrict__ BIAS,
    float* smem, float* dst, int tid, int wm, int wn, int g, int t)
{
    float acc[2][4][4];
#pragma unroll
    for (int i = 0; i < 2; i++)
#pragma unroll
        for (int j = 0; j < 4; j++)
#pragma unroll
            for (int q = 0; q < 4; q++) acc[i][j][q] = 0.0f;

    f_copy_chunk(x, m0, W, 0,  smem,         smem + ASZ,         tid);
    f_copy_chunk(x, m0, W, 32, smem + BUFSZ, smem + BUFSZ + ASZ, tid);
    cp_wait<1>();
    __syncthreads();

#pragma unroll
    for (int c = 0; c < 4; c++) {
        const float* As = smem + (c & 1) * BUFSZ;
        const float* Bs = As + ASZ;
        f_compute_chunk(As, Bs, acc, wm, wn, g, t);
        __syncthreads();
        if (c + 2 < 4) {
            float* Ad = smem + (c & 1) * BUFSZ;
            f_copy_chunk(x, m0, W, (c + 2) * 32, Ad, Ad + ASZ, tid);
        }
        if (c + 1 < 4) {
            if (c + 2 < 4) cp_wait<1>(); else cp_wait<0>();
        }
        __syncthreads();
    }

    // epilogue: acc + bias -> dst[row][col], pitch FP
#pragma unroll
    for (int nf = 0; nf < 4; nf++) {
        const int col = wn * 32 + nf * 8 + 2 * t;
        const float2 bv2 = *(const float2*)&BIAS[col];
#pragma unroll
        for (int mf = 0; mf < 2; mf++) {
            const int row0 = wm * 32 + mf * 16 + g;
            float2 o0, o1;
            o0.x = acc[mf][nf][0] + bv2.x; o0.y = acc[mf][nf][1] + bv2.y;
            o1.x = acc[mf][nf][2] + bv2.x; o1.y = acc[mf][nf][3] + bv2.y;
            *(float2*)&dst[row0 * FP + col] = o0;
            *(float2*)&dst[(row0 + 8) * FP + col] = o1;
        }
    }
}

__global__ __launch_bounds__(512, 1)
void k_fused_attn(const float* __restrict__ x,
                  const float* __restrict__ wq, const float* __restrict__ bq,
                  const float* __restrict__ wk, const float* __restrict__ bk,
                  const float* __restrict__ wv, const float* __restrict__ bv,
                  const float* __restrict__ ln1g, const float* __restrict__ ln1b)
{
    extern __shared__ float smem[];
    __shared__ float sinT[SEQ][8];
    __shared__ float cosT[SEQ][8];

    float* stage = smem;
    float* Kbuf  = smem + F_KBUF;
    float* Vbuf  = smem + F_VBUF;
    float* Qbuf  = stage;   // aliases staging; written by last GEMM's epilogue

    const int tid = threadIdx.x;
    const int warp = tid >> 5, lane = tid & 31;
    const int wm = warp >> 2, wn = warp & 3;
    const int g = lane >> 2, t = lane & 3;
    const int m0 = blockIdx.x * 128;

    if (tid < SEQ * 8) {
        const int s = tid >> 3, j = tid & 7;
        const float ang = powf(10000.0f, -(float)j / 7.0f);
        float sv, cv;
        sincosf((float)s * ang, &sv, &cv);
        sinT[s][j] = sv;
        cosT[s][j] = cv;
    }

    // GEMMs: K -> Kbuf, V -> Vbuf, Q -> Qbuf
    f_gemm_to_smem(x, m0, wk, bk, stage, Kbuf, tid, wm, wn, g, t);
    f_gemm_to_smem(x, m0, wv, bv, stage, Vbuf, tid, wm, wn, g, t);
    f_gemm_to_smem(x, m0, wq, bq, stage, Qbuf, tid, wm, wn, g, t);
    __syncthreads();

    // In-place rotary on Qbuf and Kbuf
#pragma unroll
    for (int task = tid; task < 128 * NHEAD; task += 512) {
        const int row = task >> 3, h = task & 7;
        const int s = row & 31;
        float tq[HD], tk[HD];
#pragma unroll
        for (int d4 = 0; d4 < 4; d4++) {
            *(float4*)&tq[d4 * 4] = *(const float4*)&Qbuf[row * FP + h * 16 + d4 * 4];
            *(float4*)&tk[d4 * 4] = *(const float4*)&Kbuf[row * FP + h * 16 + d4 * 4];
        }
        float rq[HD], rk[HD];
#pragma unroll
        for (int d = 0; d < HD; d++) {
            const float sv = sinT[s][d >> 1];
            const float cv = cosT[s][d >> 1];
            const int pc = (d < 8) ? (2 * d + 1) : (2 * d - 16);
            const float sgn = (d < 8) ? -1.0f : 1.0f;
            rq[d] = tq[d] * cv + sgn * tq[pc] * sv;
            rk[d] = tk[d] * cv + sgn * tk[pc] * sv;
        }
#pragma unroll
        for (int d4 = 0; d4 < 4; d4++) {
            *(float4*)&Qbuf[row * FP + h * 16 + d4 * 4] = *(const float4*)&rq[d4 * 4];
            *(float4*)&Kbuf[row * FP + h * 16 + d4 * 4] = *(const float4*)&rk[d4 * 4];
        }
    }
    __syncthreads();

    // Attention: warp w -> head h = w&7, locations l = (w>>3)*2 + step.
    // All Qbuf reads/writes of a warp are confined to its own (l, head) slice,
    // so no cross-warp barrier is needed inside the step loop.
    const int h = warp & 7;
    const float decay = log1pf(-exp2f(-(1.0f + 3.0f * (float)h / 8.0f)));

#pragma unroll
    for (int step = 0; step < 2; step++) {
        const int l = (warp >> 3) * 2 + step;
        const int qrow = l * 32 + lane;

        u64t q2[8];
        {
            const float* qp = &Qbuf[qrow * FP + h * 16];
            ulonglong2 qa = *(const ulonglong2*)(qp);
            ulonglong2 qb = *(const ulonglong2*)(qp + 4);
            ulonglong2 qc = *(const ulonglong2*)(qp + 8);
            ulonglong2 qd = *(const ulonglong2*)(qp + 12);
            q2[0] = qa.x; q2[1] = qa.y; q2[2] = qb.x; q2[3] = qb.y;
            q2[4] = qc.x; q2[5] = qc.y; q2[6] = qd.x; q2[7] = qd.y;
        }

        float p[SEQ];
        float mx = -1e30f;
#pragma unroll
        for (int j = 0; j < SEQ; j++) {
            const float* kp = &Kbuf[(l * 32 + j) * FP + h * 16];
            ulonglong2 ka = *(const ulonglong2*)(kp);
            ulonglong2 kb = *(const ulonglong2*)(kp + 4);
            ulonglong2 kc = *(const ulonglong2*)(kp + 8);
            ulonglong2 kd = *(const ulonglong2*)(kp + 12);
            u64t s2 = 0ull;  // (0.0f, 0.0f)
            fma2(s2, q2[0], ka.x); fma2(s2, q2[1], ka.y);
            fma2(s2, q2[2], kb.x); fma2(s2, q2[3], kb.y);
            fma2(s2, q2[4], kc.x); fma2(s2, q2[5], kc.y);
            fma2(s2, q2[6], kd.x); fma2(s2, q2[7], kd.y);
            float lo, hi;
            upk2(s2, lo, hi);
            const float dot = lo + hi + fabsf((float)(lane - j)) * decay;
            p[j] = dot;
            mx = fmaxf(mx, dot);
        }
        float sum = 0.0f;
#pragma unroll
        for (int j = 0; j < SEQ; j++) { p[j] = expf(p[j] - mx); sum += p[j]; }
        const float inv = 1.0f / sum;

        u64t o2[8];
#pragma unroll
        for (int i = 0; i < 8; i++) o2[i] = 0ull;
#pragma unroll
        for (int j = 0; j < SEQ; j++) {
            const float* vp = &Vbuf[(l * 32 + j) * FP + h * 16];
            ulonglong2 va = *(const ulonglong2*)(vp);
            ulonglong2 vb = *(const ulonglong2*)(vp + 4);
            ulonglong2 vc = *(const ulonglong2*)(vp + 8);
            ulonglong2 vd = *(const ulonglong2*)(vp + 12);
            const u64t pj2 = pk2(p[j], p[j]);
            fma2(o2[0], va.x, pj2); fma2(o2[1], va.y, pj2);
            fma2(o2[2], vb.x, pj2); fma2(o2[3], vb.y, pj2);
            fma2(o2[4], vc.x, pj2); fma2(o2[5], vc.y, pj2);
            fma2(o2[6], vd.x, pj2); fma2(o2[7], vd.y, pj2);
        }
        float o[HD];
#pragma unroll
        for (int i = 0; i < 8; i++) {
            float lo, hi;
            upk2(o2[i], lo, hi);
            o[2 * i] = lo * inv;
            o[2 * i + 1] = hi * inv;
        }
#pragma unroll
        for (int d4 = 0; d4 < 4; d4++)
            *(float4*)&Qbuf[qrow * FP + h * 16 + d4 * 4] = *(const float4*)&o[d4 * 4];
    }
    __syncthreads();

    // residual + LN1 -> g_x1 ; 16 warps x 8 rows
#pragma unroll
    for (int rr = 0; rr < 8; rr++) {
        const int row = warp * 8 + rr;
        const int r = m0 + row;
        const int c = lane * 4;
        float4 ov = *(const float4*)&Qbuf[row * FP + c];
        float4 xv = *(const float4*)&x[(size_t)(r & 31) * (NLOC * CDIM) + (size_t)(r >> 5) * CDIM + c];
        float v0 = ov.x + xv.x, v1 = ov.y + xv.y, v2 = ov.z + xv.z, v3 = ov.w + xv.w;
        float sum = v0 + v1 + v2 + v3;
        float sq  = v0 * v0 + v1 * v1 + v2 * v2 + v3 * v3;
#pragma unroll
        for (int off = 16; off > 0; off >>= 1) {
            sum += __shfl_xor_sync(0xffffffffu, sum, off);
            sq  += __shfl_xor_sync(0xffffffffu, sq,  off);
        }
        const float mu  = sum * (1.0f / 128.0f);
        const float var = sq * (1.0f / 128.0f) - mu * mu;
        const float wnr = rsqrtf(var + 1e-5f);
        float4 g4 = *(const float4*)&ln1g[c];
        float4 b4 = *(const float4*)&ln1b[c];
        float4 o;
        o.x = (v0 - mu) * wnr * g4.x + b4.x;
        o.y = (v1 - mu) * wnr * g4.y + b4.y;
        o.z = (v2 - mu) * wnr * g4.z + b4.z;
        o.w = (v3 - mu) * wnr * g4.w + b4.w;
        *(float4*)&g_x1[(size_t)r * CDIM + c] = o;
    }
}

// ============================================================
// Kernel 3: FFN1 H = relu(X1 @ W1 + b1)   (tf32 MMA, cp.async)
// ============================================================
__global__ __launch_bounds__(256, 2)
void k_ffn1(const float* __restrict__ w1, const float* __restrict__ b1)
{
    extern __shared__ float smem[];
    const int tid = threadIdx.x;
    const int warp = tid >> 5, lane = tid & 31;
    const int wm = warp >> 2, wn = warp & 3;
    const int g = lane >> 2, t = lane & 3;
    const int m0 = blockIdx.x * 128;
    const int bn0 = blockIdx.y * 128;

    float acc[4][4][4];
    run_gemm<4>(g_x1, CDIM, m0, w1 + bn0, FFND, acc, smem, tid, wm, wn, g, t);

#pragma unroll
    for (int nf = 0; nf < 4; nf++) {
        const int col = wn * 32 + nf * 8 + 2 * t;
        const float2 bv2 = *(const float2*)&b1[bn0 + col];
#pragma unroll
        for (int mf = 0; mf < 4; mf++) {
            const int r0 = m0 + wm * 64 + mf * 16 + g;
            float2 o0, o1;
            o0.x = fmaxf(acc[mf][nf][0] + bv2.x, 0.0f);
            o0.y = fmaxf(acc[mf][nf][1] + bv2.y, 0.0f);
            o1.x = fmaxf(acc[mf][nf][2] + bv2.x, 0.0f);
            o1.y = fmaxf(acc[mf][nf][3] + bv2.y, 0.0f);
            *(float2*)&g_h[(size_t)r0 * FFND + bn0 + col] = o0;
            *(float2*)&g_h[(size_t)(r0 + 8) * FFND + bn0 + col] = o1;
        }
    }
}

// ============================================================
// Kernel 4: FFN2 + residual + LN2 + transposed output
// ============================================================
#define TP 132
__global__ __launch_bounds__(256, 2)
void k_ffn2(const float* __restrict__ w2, const float* __restrict__ b2,
            const float* __restrict__ ln2g, const float* __restrict__ ln2b,
            float* __restrict__ out)
{
    extern __shared__ float smem[];
    const int tid = threadIdx.x;
    const int warp = tid >> 5, lane = tid & 31;
    const int wm = warp >> 2, wn = warp & 3;
    const int g = lane >> 2, t = lane & 3;
    const int m0 = blockIdx.x * 128;

    float acc[4][4][4];
    run_gemm<16>(g_h, FFND, m0, w2, CDIM, acc, smem, tid, wm, wn, g, t);

    float* T = smem;   // reuse staging (all cp.async drained, loop ends synced)
#pragma unroll
    for (int nf = 0; nf < 4; nf++) {
        const int col = wn * 32 + nf * 8 + 2 * t;
        const float2 bv2 = *(const float2*)&b2[col];
#pragma unroll
        for (int mf = 0; mf < 4; mf++) {
            const int row0 = wm * 64 + mf * 16 + g;
            float2 o0, o1;
            o0.x = acc[mf][nf][0] + bv2.x; o0.y = acc[mf][nf][1] + bv2.y;
            o1.x = acc[mf][nf][2] + bv2.x; o1.y = acc[mf][nf][3] + bv2.y;
            *(float2*)&T[row0 * TP + col] = o0;
            *(float2*)&T[(row0 + 8) * TP + col] = o1;
        }
    }
    __syncthreads();

#pragma unroll
    for (int rr = 0; rr < 16; rr++) {
        const int row = warp * 16 + rr;
        const int r = m0 + row;
        const int c = lane * 4;
        float4 v = *(const float4*)&T[row * TP + c];
        float4 xv = *(const float4*)&g_x1[(size_t)r * CDIM + c];
        float v0 = v.x + xv.x, v1 = v.y + xv.y, v2 = v.z + xv.z, v3 = v.w + xv.w;
        float sum = v0 + v1 + v2 + v3;
        float sq  = v0 * v0 + v1 * v1 + v2 * v2 + v3 * v3;
#pragma unroll
        for (int off = 16; off > 0; off >>= 1) {
            sum += __shfl_xor_sync(0xffffffffu, sum, off);
            sq  += __shfl_xor_sync(0xffffffffu, sq,  off);
        }
        const float mu  = sum * (1.0f / 128.0f);
        const float var = sq * (1.0f / 128.0f) - mu * mu;
        const float wnr = rsqrtf(var + 1e-5f);
        float4 g4 = *(const float4*)&ln2g[c];
        float4 b4 = *(const float4*)&ln2b[c];
        float4 o;
        o.x = (v0 - mu) * wnr * g4.x + b4.x;
        o.y = (v1 - mu) * wnr * g4.y + b4.y;
        o.z = (v2 - mu) * wnr * g4.z + b4.z;
        o.w = (v3 - mu) * wnr * g4.w + b4.w;
        const int nn = r >> 5;
        const int ss = r & 31;
        *(float4*)&out[(size_t)ss * NLOC * CDIM + (size_t)nn * CDIM + c] = o;
    }
}

// ============================================================
extern "C" void kernel_launch(void* const* d_in, const int* in_sizes, int n_in,
                              void* d_out, int out_size)
{
    (void)in_sizes; (void)n_in; (void)out_size;
    const float* x    = (const float*)d_in[0];
    const float* wq   = (const float*)d_in[1];
    const float* bq   = (const float*)d_in[2];
    const float* wk   = (const float*)d_in[3];
    const float* bk   = (const float*)d_in[4];
    const float* wv   = (const float*)d_in[5];
    const float* bv   = (const float*)d_in[6];
    const float* ln1g = (const float*)d_in[7];
    const float* ln1b = (const float*)d_in[8];
    const float* w1   = (const float*)d_in[9];
    const float* b1   = (const float*)d_in[10];
    const float* w2   = (const float*)d_in[11];
    const float* b2   = (const float*)d_in[12];
    const float* ln2g = (const float*)d_in[13];
    const float* ln2b = (const float*)d_in[14];
    float* out = (float*)d_out;

    cudaFuncSetAttribute(k_fused_attn, cudaFuncAttributeMaxDynamicSharedMemorySize, F_SMEM_BYTES);
    cudaFuncSetAttribute(k_ffn1, cudaFuncAttributeMaxDynamicSharedMemorySize, G3_SMEM_BYTES);
    cudaFuncSetAttribute(k_ffn2, cudaFuncAttributeMaxDynamicSharedMemorySize, G3_SMEM_BYTES);

    k_fused_attn<<<MROWS / 128, 512, F_SMEM_BYTES>>>(x, wq, bq, wk, bk, wv, bv, ln1g, ln1b);

    dim3 g3(MROWS / 128, 4);
    k_ffn1<<<g3, 256, G3_SMEM_BYTES>>>(w1, b1);

    k_ffn2<<<MROWS / 128, 256, G3_SMEM_BYTES>>>(w2, b2, ln2g, ln2b, out);
}

// round 6
// speedup vs baseline: 2.9745x; 1.0426x over previous
#include <cuda_runtime.h>
#include <math.h>

#define NLOC 8192
#define SEQ 32
#define CDIM 128
#define NHEAD 8
#define HD 16
#define MROWS (NLOC*SEQ)   // 262144
#define FFND 512

// -------- scratch (static device globals; no runtime allocation) --------
__device__ float g_x1[(size_t)MROWS * CDIM];  // 128 MB
__device__ float g_h[(size_t)MROWS * FFND];   // 512 MB

// ======================= mma / cp.async helpers =======================
__device__ __forceinline__ void mma8(float* c, const float* a, const float* b) {
    asm volatile(
        "mma.sync.aligned.m16n8k8.row.col.f32.tf32.tf32.f32 "
        "{%0,%1,%2,%3}, {%4,%5,%6,%7}, {%8,%9}, {%0,%1,%2,%3};"
        : "+f"(c[0]), "+f"(c[1]), "+f"(c[2]), "+f"(c[3])
        : "r"(__float_as_uint(a[0])), "r"(__float_as_uint(a[1])),
          "r"(__float_as_uint(a[2])), "r"(__float_as_uint(a[3])),
          "r"(__float_as_uint(b[0])), "r"(__float_as_uint(b[1])));
}

__device__ __forceinline__ void cp16(void* s, const void* g) {
    unsigned saddr = (unsigned)__cvta_generic_to_shared(s);
    asm volatile("cp.async.cg.shared.global [%0], [%1], 16;" :: "r"(saddr), "l"(g));
}
__device__ __forceinline__ void cp_commit() {
    asm volatile("cp.async.commit_group;");
}
template<int N>
__device__ __forceinline__ void cp_wait() {
    asm volatile("cp.async.wait_group %0;" :: "n"(N));
}

// packed f32x2
typedef unsigned long long u64t;
__device__ __forceinline__ u64t pk2(float lo, float hi) {
    u64t r; asm("mov.b64 %0,{%1,%2};" : "=l"(r) : "f"(lo), "f"(hi)); return r;
}
__device__ __forceinline__ void upk2(u64t v, float& lo, float& hi) {
    asm("mov.b64 {%0,%1},%2;" : "=f"(lo), "=f"(hi) : "l"(v));
}
__device__ __forceinline__ void fma2(u64t& d, u64t a, u64t b) {
    asm("fma.rn.f32x2 %0,%1,%2,%0;" : "+l"(d) : "l"(a), "l"(b));
}

// ================== 256-thread GEMM machinery (FFN kernels) ==================
// CTA tile 128x128, 8 warps, warp tile 64x32, K chunk 32, 3-stage cp.async.
#define AP 36
#define BP 136
#define ASZ (128*AP)
#define BSZ (32*BP)
#define BUFSZ (ASZ+BSZ)          // 8960 floats per stage
#define G3_SMEM_FLOATS (3*BUFSZ) // 26880 floats
#define G3_SMEM_BYTES (G3_SMEM_FLOATS*4)   // 107520 B

__device__ __forceinline__ void copy_chunk_256(
    const float* __restrict__ A, size_t lda, int m0,
    const float* __restrict__ B, int ldb, int k0,
    float* As, float* Bs, int tid)
{
    const int ia = tid >> 3;            // 0..31
    const int kc = (tid & 7) * 4;       // 0..28
#pragma unroll
    for (int p = 0; p < 4; p++)
        cp16(&As[(ia + 32 * p) * AP + kc],
             &A[(size_t)(m0 + ia + 32 * p) * lda + k0 + kc]);
    const int nb = (tid & 7) * 4;
#pragma unroll
    for (int p = 0; p < 4; p++)
        cp16(&Bs[ia * BP + nb + 32 * p],
             &B[(size_t)(k0 + ia) * ldb + nb + 32 * p]);
    cp_commit();
}

__device__ __forceinline__ void compute_chunk(
    const float* __restrict__ As, const float* __restrict__ Bs,
    float acc[4][4][4], int wm, int wn, int g, int t)
{
#pragma unroll
    for (int ks = 0; ks < 4; ks++) {
        const int kk = ks * 8;
        float b[4][2];
#pragma unroll
        for (int nf = 0; nf < 4; nf++) {
            const int n = wn * 32 + nf * 8 + g;
            b[nf][0] = Bs[(kk + t) * BP + n];
            b[nf][1] = Bs[(kk + t + 4) * BP + n];
        }
#pragma unroll
        for (int mf = 0; mf < 4; mf++) {
            const int row = wm * 64 + mf * 16 + g;
            float a[4];
            a[0] = As[row * AP + kk + t];
            a[1] = As[(row + 8) * AP + kk + t];
            a[2] = As[row * AP + kk + t + 4];
            a[3] = As[(row + 8) * AP + kk + t + 4];
#pragma unroll
            for (int nf = 0; nf < 4; nf++)
                mma8(acc[mf][nf], a, b[nf]);
        }
    }
}

template<int NC>
__device__ __forceinline__ void run_gemm(
    const float* __restrict__ A, size_t lda, int m0,
    const float* __restrict__ B, int ldb,
    float acc[4][4][4], float* smem, int tid,
    int wm, int wn, int g, int t)
{
#pragma unroll
    for (int i = 0; i < 4; i++)
#pragma unroll
        for (int j = 0; j < 4; j++)
#pragma unroll
            for (int q = 0; q < 4; q++) acc[i][j][q] = 0.0f;

    copy_chunk_256(A, lda, m0, B, ldb, 0, smem, smem + ASZ, tid);
    if (NC > 1)
        copy_chunk_256(A, lda, m0, B, ldb, 32, smem + BUFSZ, smem + BUFSZ + ASZ, tid);
    cp_wait<(NC > 1) ? 1 : 0>();
    __syncthreads();

    int bc = 0;                 // buffer of chunk c (c % 3)
#pragma unroll 1
    for (int c = 0; c < NC; c++) {
        const float* As = smem + bc * BUFSZ;
        const float* Bs = As + ASZ;
        compute_chunk(As, Bs, acc, wm, wn, g, t);
        __syncthreads();
        if (c + 2 < NC) {
            int bl = bc + 2; if (bl >= 3) bl -= 3;
            float* Ad = smem + bl * BUFSZ;
            copy_chunk_256(A, lda, m0, B, ldb, (c + 2) * 32, Ad, Ad + ASZ, tid);
        }
        if (c + 1 < NC) {
            if (c + 2 < NC) cp_wait<1>(); else cp_wait<0>();
        }
        __syncthreads();
        if (++bc == 3) bc = 0;
    }
}

// ============================================================
// Kernel 1 (FUSED): merged QKV GEMM + rotary + attention + residual + LN1
// 512 threads, 16 warps as 4x4; warp tile 32 rows x 32 cols PER WEIGHT.
// One A staging shared by the 3 weight GEMMs; 3 accumulator sets.
// smem: [stage 2*(A+3B) = 35328 f][Qbuf 16896 f]; Kbuf/Vbuf overlay stage.
// ============================================================
#define FP 132
#define M_ASZ (128*AP)             // 4608
#define M_BSZ (32*BP)              // 4352
#define M_BUF (M_ASZ + 3*M_BSZ)    // 17664 floats per stage
#define M_STAGE (2*M_BUF)          // 35328 floats
#define M_KBUF 0                   // overlays stage[0..16896)
#define M_VBUF 16896               // overlays stage[16896..33792)
#define M_QBUF M_STAGE             // dedicated
#define M_SMEM_FLOATS (M_STAGE + 128*FP)   // 52224 floats
#define M_SMEM_BYTES (M_SMEM_FLOATS*4)     // 208896 B

__device__ __forceinline__ void m_copy_chunk(
    const float* __restrict__ x, int m0,
    const float* __restrict__ wk, const float* __restrict__ wv,
    const float* __restrict__ wq, int k0, float* buf, int tid)
{
    // A: 128 rows x 32 k  (gathered from x: row r -> x[r&31][r>>5][:])
    const int ia = tid >> 2;            // 0..127
    const int kc = (tid & 3) * 8;       // 0,8,16,24
    const int r = m0 + ia;
    const size_t off = (size_t)(r & 31) * (NLOC * CDIM) + (size_t)(r >> 5) * CDIM;
    cp16(&buf[ia * AP + kc],     &x[off + k0 + kc]);
    cp16(&buf[ia * AP + kc + 4], &x[off + k0 + kc + 4]);
    // B x3: each 32 k-rows x 128 cols
    const int kr = tid >> 4;            // 0..31
    const int nb = (tid & 15) * 8;      // 0..120
    const float* Ws[3] = { wk, wv, wq };
#pragma unroll
    for (int w = 0; w < 3; w++) {
        float* Bs = buf + M_ASZ + w * M_BSZ;
        cp16(&Bs[kr * BP + nb],     &Ws[w][(size_t)(k0 + kr) * CDIM + nb]);
        cp16(&Bs[kr * BP + nb + 4], &Ws[w][(size_t)(k0 + kr) * CDIM + nb + 4]);
    }
    cp_commit();
}

__device__ __forceinline__ void m_compute_chunk(
    const float* __restrict__ buf,
    float acc[3][2][4][4], int wm, int wn, int g, int t)
{
    const float* As = buf;
#pragma unroll
    for (int ks = 0; ks < 4; ks++) {
        const int kk = ks * 8;
        float a[2][4];
#pragma unroll
        for (int mf = 0; mf < 2; mf++) {
            const int row = wm * 32 + mf * 16 + g;
            a[mf][0] = As[row * AP + kk + t];
            a[mf][1] = As[(row + 8) * AP + kk + t];
            a[mf][2] = As[row * AP + kk + t + 4];
            a[mf][3] = As[(row + 8) * AP + kk + t + 4];
        }
#pragma unroll
        for (int w = 0; w < 3; w++) {
            const float* Bs = buf + M_ASZ + w * M_BSZ;
#pragma unroll
            for (int nf = 0; nf < 4; nf++) {
                const int n = wn * 32 + nf * 8 + g;
                float b[2];
                b[0] = Bs[(kk + t) * BP + n];
                b[1] = Bs[(kk + t + 4) * BP + n];
#pragma unroll
                for (int mf = 0; mf < 2; mf++)
                    mma8(acc[w][mf][nf], a[mf], b);
            }
        }
    }
}

__global__ __launch_bounds__(512, 1)
void k_fused_attn(const float* __restrict__ x,
                  const float* __restrict__ wq, const float* __restrict__ bq,
                  const float* __restrict__ wk, const float* __restrict__ bk,
                  const float* __restrict__ wv, const float* __restrict__ bv,
                  const float* __restrict__ ln1g, const float* __restrict__ ln1b)
{
    extern __shared__ float smem[];
    __shared__ float sinT[SEQ][8];
    __shared__ float cosT[SEQ][8];

    float* Kbuf = smem + M_KBUF;
    float* Vbuf = smem + M_VBUF;
    float* Qbuf = smem + M_QBUF;

    const int tid = threadIdx.x;
    const int warp = tid >> 5, lane = tid & 31;
    const int wm = warp >> 2, wn = warp & 3;       // 4x4 warp grid
    const int g = lane >> 2, t = lane & 3;
    const int m0 = blockIdx.x * 128;

    if (tid < SEQ * 8) {
        const int s = tid >> 3, j = tid & 7;
        const float ang = powf(10000.0f, -(float)j / 7.0f);
        float sv, cv;
        sincosf((float)s * ang, &sv, &cv);
        sinT[s][j] = sv;
        cosT[s][j] = cv;
    }

    // ---------- merged QKV mainloop (4 chunks, double-buffered) ----------
    float acc[3][2][4][4];
#pragma unroll
    for (int w = 0; w < 3; w++)
#pragma unroll
        for (int i = 0; i < 2; i++)
#pragma unroll
            for (int j = 0; j < 4; j++)
#pragma unroll
                for (int q = 0; q < 4; q++) acc[w][i][j][q] = 0.0f;

    m_copy_chunk(x, m0, wk, wv, wq, 0,  smem,         tid);
    m_copy_chunk(x, m0, wk, wv, wq, 32, smem + M_BUF, tid);
    cp_wait<1>();
    __syncthreads();

#pragma unroll
    for (int c = 0; c < 4; c++) {
        const float* buf = smem + (c & 1) * M_BUF;
        m_compute_chunk(buf, acc, wm, wn, g, t);
        __syncthreads();
        if (c + 2 < 4)
            m_copy_chunk(x, m0, wk, wv, wq, (c + 2) * 32, smem + (c & 1) * M_BUF, tid);
        if (c + 1 < 4) {
            if (c + 2 < 4) cp_wait<1>(); else cp_wait<0>();
        }
        __syncthreads();
    }

    // ---------- epilogue: acc + bias -> K/V/Q smem tiles ----------
    {
        const float* biases[3] = { bk, bv, bq };
        float* dsts[3] = { Kbuf, Vbuf, Qbuf };
#pragma unroll
        for (int w = 0; w < 3; w++) {
            float* dst = dsts[w];
            const float* BIAS = biases[w];
#pragma unroll
            for (int nf = 0; nf < 4; nf++) {
                const int col = wn * 32 + nf * 8 + 2 * t;
                const float2 bv2 = *(const float2*)&BIAS[col];
#pragma unroll
                for (int mf = 0; mf < 2; mf++) {
                    const int row0 = wm * 32 + mf * 16 + g;
                    float2 o0, o1;
                    o0.x = acc[w][mf][nf][0] + bv2.x; o0.y = acc[w][mf][nf][1] + bv2.y;
                    o1.x = acc[w][mf][nf][2] + bv2.x; o1.y = acc[w][mf][nf][3] + bv2.y;
                    *(float2*)&dst[row0 * FP + col] = o0;
                    *(float2*)&dst[(row0 + 8) * FP + col] = o1;
                }
            }
        }
    }
    __syncthreads();

    // ---------- in-place rotary on Qbuf and Kbuf ----------
#pragma unroll
    for (int task = tid; task < 128 * NHEAD; task += 512) {
        const int row = task >> 3, h = task & 7;
        const int s = row & 31;
        float tq[HD], tk[HD];
#pragma unroll
        for (int d4 = 0; d4 < 4; d4++) {
            *(float4*)&tq[d4 * 4] = *(const float4*)&Qbuf[row * FP + h * 16 + d4 * 4];
            *(float4*)&tk[d4 * 4] = *(const float4*)&Kbuf[row * FP + h * 16 + d4 * 4];
        }
        float rq[HD], rk[HD];
#pragma unroll
        for (int d = 0; d < HD; d++) {
            const float sv = sinT[s][d >> 1];
            const float cv = cosT[s][d >> 1];
            const int pc = (d < 8) ? (2 * d + 1) : (2 * d - 16);
            const float sgn = (d < 8) ? -1.0f : 1.0f;
            rq[d] = tq[d] * cv + sgn * tq[pc] * sv;
            rk[d] = tk[d] * cv + sgn * tk[pc] * sv;
        }
#pragma unroll
        for (int d4 = 0; d4 < 4; d4++) {
            *(float4*)&Qbuf[row * FP + h * 16 + d4 * 4] = *(const float4*)&rq[d4 * 4];
            *(float4*)&Kbuf[row * FP + h * 16 + d4 * 4] = *(const float4*)&rk[d4 * 4];
        }
    }
    __syncthreads();

    // ---------- attention: warp -> (head, 2 locations) ----------
    const int h = warp & 7;
    const float decay = log1pf(-exp2f(-(1.0f + 3.0f * (float)h / 8.0f)));

#pragma unroll
    for (int step = 0; step < 2; step++) {
        const int l = (warp >> 3) * 2 + step;
        const int qrow = l * 32 + lane;

        u64t q2[8];
        {
            const float* qp = &Qbuf[qrow * FP + h * 16];
            ulonglong2 qa = *(const ulonglong2*)(qp);
            ulonglong2 qb = *(const ulonglong2*)(qp + 4);
            ulonglong2 qc = *(const ulonglong2*)(qp + 8);
            ulonglong2 qd = *(const ulonglong2*)(qp + 12);
            q2[0] = qa.x; q2[1] = qa.y; q2[2] = qb.x; q2[3] = qb.y;
            q2[4] = qc.x; q2[5] = qc.y; q2[6] = qd.x; q2[7] = qd.y;
        }

        float p[SEQ];
        float mx = -1e30f;
#pragma unroll
        for (int j = 0; j < SEQ; j++) {
            const float* kp = &Kbuf[(l * 32 + j) * FP + h * 16];
            ulonglong2 ka = *(const ulonglong2*)(kp);
            ulonglong2 kb = *(const ulonglong2*)(kp + 4);
            ulonglong2 kc = *(const ulonglong2*)(kp + 8);
            ulonglong2 kd = *(const ulonglong2*)(kp + 12);
            u64t s2 = 0ull;
            fma2(s2, q2[0], ka.x); fma2(s2, q2[1], ka.y);
            fma2(s2, q2[2], kb.x); fma2(s2, q2[3], kb.y);
            fma2(s2, q2[4], kc.x); fma2(s2, q2[5], kc.y);
            fma2(s2, q2[6], kd.x); fma2(s2, q2[7], kd.y);
            float lo, hi;
            upk2(s2, lo, hi);
            const float dot = lo + hi + fabsf((float)(lane - j)) * decay;
            p[j] = dot;
            mx = fmaxf(mx, dot);
        }
        float sum = 0.0f;
#pragma unroll
        for (int j = 0; j < SEQ; j++) { p[j] = expf(p[j] - mx); sum += p[j]; }
        const float inv = 1.0f / sum;

        u64t o2[8];
#pragma unroll
        for (int i = 0; i < 8; i++) o2[i] = 0ull;
#pragma unroll
        for (int j = 0; j < SEQ; j++) {
            const float* vp = &Vbuf[(l * 32 + j) * FP + h * 16];
            ulonglong2 va = *(const ulonglong2*)(vp);
            ulonglong2 vb = *(const ulonglong2*)(vp + 4);
            ulonglong2 vc = *(const ulonglong2*)(vp + 8);
            ulonglong2 vd = *(const ulonglong2*)(vp + 12);
            const u64t pj2 = pk2(p[j], p[j]);
            fma2(o2[0], va.x, pj2); fma2(o2[1], va.y, pj2);
            fma2(o2[2], vb.x, pj2); fma2(o2[3], vb.y, pj2);
            fma2(o2[4], vc.x, pj2); fma2(o2[5], vc.y, pj2);
            fma2(o2[6], vd.x, pj2); fma2(o2[7], vd.y, pj2);
        }
        float o[HD];
#pragma unroll
        for (int i = 0; i < 8; i++) {
            float lo, hi;
            upk2(o2[i], lo, hi);
            o[2 * i] = lo * inv;
            o[2 * i + 1] = hi * inv;
        }
#pragma unroll
        for (int d4 = 0; d4 < 4; d4++)
            *(float4*)&Qbuf[qrow * FP + h * 16 + d4 * 4] = *(const float4*)&o[d4 * 4];
    }
    __syncthreads();

    // ---------- residual + LN1 -> g_x1 ----------
#pragma unroll
    for (int rr = 0; rr < 8; rr++) {
        const int row = warp * 8 + rr;
        const int r = m0 + row;
        const int c = lane * 4;
        float4 ov = *(const float4*)&Qbuf[row * FP + c];
        float4 xv = *(const float4*)&x[(size_t)(r & 31) * (NLOC * CDIM) + (size_t)(r >> 5) * CDIM + c];
        float v0 = ov.x + xv.x, v1 = ov.y + xv.y, v2 = ov.z + xv.z, v3 = ov.w + xv.w;
        float sum = v0 + v1 + v2 + v3;
        float sq  = v0 * v0 + v1 * v1 + v2 * v2 + v3 * v3;
#pragma unroll
        for (int off = 16; off > 0; off >>= 1) {
            sum += __shfl_xor_sync(0xffffffffu, sum, off);
            sq  += __shfl_xor_sync(0xffffffffu, sq,  off);
        }
        const float mu  = sum * (1.0f / 128.0f);
        const float var = sq * (1.0f / 128.0f) - mu * mu;
        const float wnr = rsqrtf(var + 1e-5f);
        float4 g4 = *(const float4*)&ln1g[c];
        float4 b4 = *(const float4*)&ln1b[c];
        float4 o;
        o.x = (v0 - mu) * wnr * g4.x + b4.x;
        o.y = (v1 - mu) * wnr * g4.y + b4.y;
        o.z = (v2 - mu) * wnr * g4.z + b4.z;
        o.w = (v3 - mu) * wnr * g4.w + b4.w;
        *(float4*)&g_x1[(size_t)r * CDIM + c] = o;
    }
}

// ============================================================
// Kernel 3: FFN1 H = relu(X1 @ W1 + b1)   (tf32 MMA, cp.async)
// ============================================================
__global__ __launch_bounds__(256, 2)
void k_ffn1(const float* __restrict__ w1, const float* __restrict__ b1)
{
    extern __shared__ float smem[];
    const int tid = threadIdx.x;
    const int warp = tid >> 5, lane = tid & 31;
    const int wm = warp >> 2, wn = warp & 3;
    const int g = lane >> 2, t = lane & 3;
    const int m0 = blockIdx.x * 128;
    const int bn0 = blockIdx.y * 128;

    float acc[4][4][4];
    run_gemm<4>(g_x1, CDIM, m0, w1 + bn0, FFND, acc, smem, tid, wm, wn, g, t);

#pragma unroll
    for (int nf = 0; nf < 4; nf++) {
        const int col = wn * 32 + nf * 8 + 2 * t;
        const float2 bv2 = *(const float2*)&b1[bn0 + col];
#pragma unroll
        for (int mf = 0; mf < 4; mf++) {
            const int r0 = m0 + wm * 64 + mf * 16 + g;
            float2 o0, o1;
            o0.x = fmaxf(acc[mf][nf][0] + bv2.x, 0.0f);
            o0.y = fmaxf(acc[mf][nf][1] + bv2.y, 0.0f);
            o1.x = fmaxf(acc[mf][nf][2] + bv2.x, 0.0f);
            o1.y = fmaxf(acc[mf][nf][3] + bv2.y, 0.0f);
            *(float2*)&g_h[(size_t)r0 * FFND + bn0 + col] = o0;
            *(float2*)&g_h[(size_t)(r0 + 8) * FFND + bn0 + col] = o1;
        }
    }
}

// ============================================================
// Kernel 4: FFN2 + residual + LN2 + transposed output
// ============================================================
#define TP 132
__global__ __launch_bounds__(256, 2)
void k_ffn2(const float* __restrict__ w2, const float* __restrict__ b2,
            const float* __restrict__ ln2g, const float* __restrict__ ln2b,
            float* __restrict__ out)
{
    extern __shared__ float smem[];
    const int tid = threadIdx.x;
    const int warp = tid >> 5, lane = tid & 31;
    const int wm = warp >> 2, wn = warp & 3;
    const int g = lane >> 2, t = lane & 3;
    const int m0 = blockIdx.x * 128;

    float acc[4][4][4];
    run_gemm<16>(g_h, FFND, m0, w2, CDIM, acc, smem, tid, wm, wn, g, t);

    float* T = smem;   // reuse staging (all cp.async drained, loop ends synced)
#pragma unroll
    for (int nf = 0; nf < 4; nf++) {
        const int col = wn * 32 + nf * 8 + 2 * t;
        const float2 bv2 = *(const float2*)&b2[col];
#pragma unroll
        for (int mf = 0; mf < 4; mf++) {
            const int row0 = wm * 64 + mf * 16 + g;
            float2 o0, o1;
            o0.x = acc[mf][nf][0] + bv2.x; o0.y = acc[mf][nf][1] + bv2.y;
            o1.x = acc[mf][nf][2] + bv2.x; o1.y = acc[mf][nf][3] + bv2.y;
            *(float2*)&T[row0 * TP + col] = o0;
            *(float2*)&T[(row0 + 8) * TP + col] = o1;
        }
    }
    __syncthreads();

#pragma unroll
    for (int rr = 0; rr < 16; rr++) {
        const int row = warp * 16 + rr;
        const int r = m0 + row;
        const int c = lane * 4;
        float4 v = *(const float4*)&T[row * TP + c];
        float4 xv = *(const float4*)&g_x1[(size_t)r * CDIM + c];
        float v0 = v.x + xv.x, v1 = v.y + xv.y, v2 = v.z + xv.z, v3 = v.w + xv.w;
        float sum = v0 + v1 + v2 + v3;
        float sq  = v0 * v0 + v1 * v1 + v2 * v2 + v3 * v3;
#pragma unroll
        for (int off = 16; off > 0; off >>= 1) {
            sum += __shfl_xor_sync(0xffffffffu, sum, off);
            sq  += __shfl_xor_sync(0xffffffffu, sq,  off);
        }
        const float mu  = sum * (1.0f / 128.0f);
        const float var = sq * (1.0f / 128.0f) - mu * mu;
        const float wnr = rsqrtf(var + 1e-5f);
        float4 g4 = *(const float4*)&ln2g[c];
        float4 b4 = *(const float4*)&ln2b[c];
        float4 o;
        o.x = (v0 - mu) * wnr * g4.x + b4.x;
        o.y = (v1 - mu) * wnr * g4.y + b4.y;
        o.z = (v2 - mu) * wnr * g4.z + b4.z;
        o.w = (v3 - mu) * wnr * g4.w + b4.w;
        const int nn = r >> 5;
        const int ss = r & 31;
        *(float4*)&out[(size_t)ss * NLOC * CDIM + (size_t)nn * CDIM + c] = o;
    }
}

// ============================================================
extern "C" void kernel_launch(void* const* d_in, const int* in_sizes, int n_in,
                              void* d_out, int out_size)
{
    (void)in_sizes; (void)n_in; (void)out_size;
    const float* x    = (const float*)d_in[0];
    const float* wq   = (const float*)d_in[1];
    const float* bq   = (const float*)d_in[2];
    const float* wk   = (const float*)d_in[3];
    const float* bk   = (const float*)d_in[4];
    const float* wv   = (const float*)d_in[5];
    const float* bv   = (const float*)d_in[6];
    const float* ln1g = (const float*)d_in[7];
    const float* ln1b = (const float*)d_in[8];
    const float* w1   = (const float*)d_in[9];
    const float* b1   = (const float*)d_in[10];
    const float* w2   = (const float*)d_in[11];
    const float* b2   = (const float*)d_in[12];
    const float* ln2g = (const float*)d_in[13];
    const float* ln2b = (const float*)d_in[14];
    float* out = (float*)d_out;

    cudaFuncSetAttribute(k_fused_attn, cudaFuncAttributeMaxDynamicSharedMemorySize, M_SMEM_BYTES);
    cudaFuncSetAttribute(k_ffn1, cudaFuncAttributeMaxDynamicSharedMemorySize, G3_SMEM_BYTES);
    cudaFuncSetAttribute(k_ffn2, cudaFuncAttributeMaxDynamicSharedMemorySize, G3_SMEM_BYTES);

    k_fused_attn<<<MROWS / 128, 512, M_SMEM_BYTES>>>(x, wq, bq, wk, bk, wv, bv, ln1g, ln1b);

    dim3 g3(MROWS / 128, 4);
    k_ffn1<<<g3, 256, G3_SMEM_BYTES>>>(w1, b1);

    k_ffn2<<<MROWS / 128, 256, G3_SMEM_BYTES>>>(w2, b2, ln2g, ln2b, out);
}